// round 11
// baseline (speedup 1.0000x reference)
#include <cuda_runtime.h>
#include <cuda_fp16.h>
#include <cstdint>

#define BB   512
#define TT   100
#define LL   256
#define DD   128
#define PP   9
#define NSEQ (BB*TT)
#define NG   512
#define MROWS 128
#define NBLK (NSEQ/MROWS)   // 400
#define NTHR 512
#define ROWB  272            // padded row stride bytes
#define CHUNK (128*ROWB)     // 34816
#define PAIRB (2*CHUNK)      // 69632: [Wih_q | Whh_q]

// SMEM layout (dynamic)
#define SM_AX   0            // 34816 x tile
#define SM_AH   34816        // 34816 h tile
#define SM_W    69632        // 2 x PAIRB ring -> ends 208896
#define SM_BIAS 208896       // 2048
#define SM_NID  210944       // 4608
#define SM_ACT  215552       // 512
#define SM_MBAR 216064       // full0 full1 free0 free1 (4 x 8B)
#define SMEM_SZ 216192

__device__ __align__(128) unsigned char g_Bimg[4*PAIRB];
__device__ float g_bias[NG];
__device__ int   g_nids[NSEQ*PP];
__device__ int   g_active[NSEQ];

__device__ __forceinline__ float sigf(float x)   { return 1.0f / (1.0f + __expf(-x)); }
__device__ __forceinline__ float tanhf_(float x) { return 1.0f - 2.0f / (__expf(2.0f*x) + 1.0f); }

__device__ __forceinline__ uint32_t smem_u32(const void* p) {
    uint32_t a;
    asm("{ .reg .u64 t; cvta.to.shared.u64 t, %1; cvt.u32.u64 %0, t; }" : "=r"(a) : "l"(p));
    return a;
}
__device__ __forceinline__ void mbar_init(uint32_t mbar, uint32_t cnt) {
    asm volatile("mbarrier.init.shared.b64 [%0], %1;" :: "r"(mbar), "r"(cnt) : "memory");
}
__device__ __forceinline__ void mbar_expect_tx(uint32_t mbar, uint32_t bytes) {
    asm volatile("mbarrier.arrive.expect_tx.shared.b64 _, [%0], %1;" :: "r"(mbar), "r"(bytes) : "memory");
}
__device__ __forceinline__ void mbar_arrive(uint32_t mbar) {
    asm volatile("mbarrier.arrive.shared.b64 _, [%0];" :: "r"(mbar) : "memory");
}
__device__ __forceinline__ void mbar_wait(uint32_t mbar, uint32_t ph) {
    asm volatile(
        "{\n\t.reg .pred P;\n\tLW_%=:\n\t"
        "mbarrier.try_wait.parity.acquire.cta.shared::cta.b64 P, [%0], %1, 0x989680;\n\t"
        "@P bra LD_%=;\n\tbra LW_%=;\n\tLD_%=:\n\t}"
        :: "r"(mbar), "r"(ph) : "memory");
}
__device__ __forceinline__ void bulk_g2s(uint32_t dst, const void* src, uint32_t bytes, uint32_t mbar) {
    asm volatile(
        "cp.async.bulk.shared::cluster.global.mbarrier::complete_tx::bytes [%0], [%1], %2, [%3];"
        :: "r"(dst), "l"(src), "r"(bytes), "r"(mbar) : "memory");
}
__device__ __forceinline__ void mma16816h(float* d, const uint32_t* a, const uint32_t* b) {
    asm volatile(
        "mma.sync.aligned.m16n8k16.row.col.f32.f16.f16.f32 "
        "{%0,%1,%2,%3}, {%4,%5,%6,%7}, {%8,%9}, {%0,%1,%2,%3};"
        : "+f"(d[0]), "+f"(d[1]), "+f"(d[2]), "+f"(d[3])
        : "r"(a[0]), "r"(a[1]), "r"(a[2]), "r"(a[3]), "r"(b[0]), "r"(b[1]));
}
__device__ __forceinline__ void ldsm4(uint32_t* r, uint32_t addr) {
    asm volatile("ldmatrix.sync.aligned.m8n8.x4.shared.b16 {%0,%1,%2,%3}, [%4];"
        : "=r"(r[0]), "=r"(r[1]), "=r"(r[2]), "=r"(r[3]) : "r"(addr));
}

// One [32m x 32n x 128k] warp product-accumulate (fp16 operands).
// abase: A tile base + per-lane ldmatrix offset. W: pointer to 128n x 128k chunk.
__device__ __forceinline__ void gemm_pass(uint32_t abase, const char* __restrict__ W,
                                          int nw, int g, int tg, float d[2][4][4]) {
#pragma unroll
    for (int k8 = 0; k8 < 8; k8++) {
        uint32_t a[2][4], b[4][2];
#pragma unroll
        for (int mi = 0; mi < 2; mi++)
            ldsm4(a[mi], abase + mi*(16*ROWB) + k8*32);
        const int kb = (k8*16 + tg*2) * 2;
#pragma unroll
        for (int ni = 0; ni < 4; ni++) {
            const char* wr = W + (nw*32 + ni*8 + g)*ROWB + kb;
            b[ni][0] = *(const uint32_t*)wr;
            b[ni][1] = *(const uint32_t*)(wr + 16);
        }
#pragma unroll
        for (int mi = 0; mi < 2; mi++)
#pragma unroll
            for (int ni = 0; ni < 4; ni++)
                mma16816h(d[mi][ni], a[mi], b[ni]);
    }
}

// ---------------------------------------------------------------------------
// prep: fp16 W image; pair q = [Wih_q | Whh_q], row n=(j&31)*4+gate, 272B rows
// ---------------------------------------------------------------------------
__global__ void prep_kernel(const float* __restrict__ w_ih, const float* __restrict__ w_hh,
                            const float* __restrict__ b_ih, const float* __restrict__ b_hh) {
    int idx = blockIdx.x * blockDim.x + threadIdx.x;
    if (idx < NG) g_bias[idx] = b_ih[idx] + b_hh[idx];
    if (idx >= 2 * NG * DD) return;
    int part = idx >> 16;          // 0: Wih, 1: Whh
    int rem  = idx & 65535;
    int r = rem >> 7;
    int k = rem & 127;
    int gate = r >> 7, j = r & 127;
    int q = j >> 5;
    int n = ((j & 31) << 2) | gate;
    float w = (part == 0) ? w_ih[r * DD + k] : w_hh[r * DD + k];
    *(__half*)((char*)g_Bimg + q*PAIRB + part*CHUNK + n*ROWB + k*2) = __float2half(w);
}

// ---------------------------------------------------------------------------
__global__ void leaf_kernel(const float* __restrict__ cross, const int* __restrict__ paths) {
    int warp = (blockIdx.x * blockDim.x + threadIdx.x) >> 5;
    int lane = threadIdx.x & 31;
    if (warp >= NSEQ) return;
    int b = warp / TT;
    int t = warp - b * TT;
    const float* row = cross + (size_t)b * (TT*LL) + (size_t)t * LL;
    float bv = -3.0e38f; int bl = 0; int anyp = 0;
#pragma unroll
    for (int i = 0; i < LL/32; i++) {
        int l = lane + 32*i;
        float v = row[l];
        if (v > 0.0f) anyp = 1;
        if (v > bv) { bv = v; bl = l; }
    }
#pragma unroll
    for (int off = 16; off > 0; off >>= 1) {
        float ov = __shfl_down_sync(0xffffffffu, bv, off);
        int   ol = __shfl_down_sync(0xffffffffu, bl, off);
        if (ov > bv || (ov == bv && ol < bl)) { bv = ov; bl = ol; }
    }
    anyp = __any_sync(0xffffffffu, anyp);
    int leaf = __shfl_sync(0xffffffffu, bl, 0);
    if (lane < PP) g_nids[warp*PP + lane] = paths[((size_t)t*LL + leaf)*PP + lane];
    if (lane == 0) g_active[warp] = anyp;
}

// dummies: position lstm_mma at profiled launch index (-s 5 -c 1)
__global__ void dummy_k() {}

// ---------------------------------------------------------------------------
__global__ void __launch_bounds__(NTHR, 1)
lstm_mma(const float* __restrict__ node_emb, float* __restrict__ out) {
    extern __shared__ __align__(16) char smem[];
    const uint32_t sb = smem_u32(smem);
    const int tid  = threadIdx.x;
    const int wid  = tid >> 5, lane = tid & 31;
    const int g    = lane >> 2, tg = lane & 3;
    const int mw   = wid >> 2, nw = wid & 3;        // 4 x 4 warp grid
    const int bt0  = blockIdx.x * MROWS;

    int* snid   = (int*)(smem + SM_NID);
    int* sact   = (int*)(smem + SM_ACT);
    float* sbias = (float*)(smem + SM_BIAS);
    for (int i = tid; i < MROWS*PP; i += NTHR) snid[i] = g_nids[bt0*PP + i];
    for (int i = tid; i < MROWS; i += NTHR)    sact[i] = g_active[bt0 + i];
    for (int i = tid; i < NG; i += NTHR)       sbias[i] = g_bias[i];
    if (tid == 0) {
        mbar_init(sb + SM_MBAR,      1);     // full0 (tx)
        mbar_init(sb + SM_MBAR + 8,  1);     // full1 (tx)
        mbar_init(sb + SM_MBAR + 16, NTHR);  // free0 (arrive-all)
        mbar_init(sb + SM_MBAR + 24, NTHR);  // free1
    }
    __syncthreads();

    const uint32_t lrow = lane & 15;
    const uint32_t lcol = (lane & 16) ? 16u : 0u;
    const uint32_t aoff = (mw*32 + lrow) * ROWB + lcol;
    const uint32_t ax_b = sb + SM_AX + aoff;
    const uint32_t ah_b = sb + SM_AH + aoff;

    const int rbase = mw*32 + g + ((tg & 1) ? 8 : 0);   // epilogue row base

    float creg[4][8], hkeep[4][8];
#pragma unroll
    for (int q = 0; q < 4; q++)
#pragma unroll
        for (int i = 0; i < 8; i++) creg[q][i] = 0.0f;

    int icnt = 0, ccnt = 0;
    int ib[2] = {0, 0};   // per-buffer issue counts (tid0 meaningful)

    auto issue = [&](int pq) {
        int b = icnt & 1;
        if (tid == 0) {
            int t = ib[b];
            if (t >= 1) mbar_wait(sb + SM_MBAR + 16 + 8*b, (t - 1) & 1);  // prev use drained
            mbar_expect_tx(sb + SM_MBAR + 8*b, PAIRB);
            bulk_g2s(sb + SM_W + b*PAIRB,
                     (const char*)g_Bimg + (size_t)pq*PAIRB, PAIRB, sb + SM_MBAR + 8*b);
            ib[b] = t + 1;
        }
        icnt++;
    };

    for (int p = 0; p < PP; p++) {
        issue(0); issue(1);   // overlap transfers with the gather below

        // ---- gather x_p into A_x (fp16) ----
#pragma unroll
        for (int i = 0; i < 8; i++) {
            int idx = i * NTHR + tid;          // 4096 float4 items
            int mm = idx >> 5, kq = (idx & 31) << 2;
            const float4 v = *(const float4*)(node_emb + (size_t)snid[mm*PP + p]*DD + kq);
            __half2 a = __floats2half2_rn(v.x, v.y);
            __half2 b = __floats2half2_rn(v.z, v.w);
            uint2 pk; pk.x = *(uint32_t*)&a; pk.y = *(uint32_t*)&b;
            *(uint2*)(smem + SM_AX + mm*ROWB + kq*2) = pk;
        }
        __syncthreads();   // x + prev-step h scatter visible to all warps

#pragma unroll
        for (int q = 0; q < 4; q++) {
            const int b = ccnt & 1;
            mbar_wait(sb + SM_MBAR + 8*b, (ccnt >> 1) & 1);   // W pair arrived
            const char* W = smem + SM_W + b*PAIRB;
            ccnt++;

            float d[2][4][4];
#pragma unroll
            for (int mi = 0; mi < 2; mi++)
#pragma unroll
                for (int ni = 0; ni < 4; ni++)
#pragma unroll
                    for (int e = 0; e < 4; e++) d[mi][ni][e] = 0.0f;

            gemm_pass(ax_b, W, nw, g, tg, d);               // x @ Wih_q
            if (p > 0)
                gemm_pass(ah_b, W + CHUNK, nw, g, tg, d);   // h @ Whh_q

            mbar_arrive(sb + SM_MBAR + 16 + 8*b);   // done with this buffer
            if (q + 2 < 4) issue(q + 2);

            // ---- epilogue for quarter q (no barrier; overlaps other warps) ----
#pragma unroll
            for (int ni = 0; ni < 4; ni++) {
                const int j = q*32 + nw*8 + ni*2 + (tg >> 1);
                const float bi = sbias[j],       bfv = sbias[128 + j];
                const float bg = sbias[256 + j], bo  = sbias[384 + j];
#pragma unroll
                for (int mi = 0; mi < 2; mi++) {
                    float d0 = d[mi][ni][0], d1 = d[mi][ni][1];
                    float d2 = d[mi][ni][2], d3 = d[mi][ni][3];
                    float s0 = __shfl_xor_sync(0xffffffffu, d0, 1);
                    float s1 = __shfl_xor_sync(0xffffffffu, d1, 1);
                    float s2 = __shfl_xor_sync(0xffffffffu, d2, 1);
                    float s3 = __shfl_xor_sync(0xffffffffu, d3, 1);
                    float gi, gf, gg, go;
                    if ((tg & 1) == 0) { gi = d0; gf = d1; gg = s0; go = s1; }
                    else               { gi = s2; gf = s3; gg = d2; go = d3; }
                    float& cc = creg[q][mi*4 + ni];
                    cc = sigf(gf + bfv) * cc + sigf(gi + bi) * tanhf_(gg + bg);
                    float h = sigf(go + bo) * tanhf_(cc);
                    hkeep[q][mi*4 + ni] = h;
                    if (p == PP - 1) {
                        const int r = rbase + mi*16;
                        out[(size_t)(bt0 + r)*DD + j] = sact[r] ? h : 0.0f;
                    }
                }
            }
        }

        if (p < PP - 1) {
            __syncthreads();   // all warps done reading A_h this step
            // scatter all h for next step (visible via next post-gather sync)
#pragma unroll
            for (int q = 0; q < 4; q++)
#pragma unroll
                for (int ni = 0; ni < 4; ni++) {
                    const int j = q*32 + nw*8 + ni*2 + (tg >> 1);
#pragma unroll
                    for (int mi = 0; mi < 2; mi++) {
                        const int r = rbase + mi*16;
                        *(__half*)(smem + SM_AH + r*ROWB + j*2) =
                            __float2half(hkeep[q][mi*4 + ni]);
                    }
                }
        }
    }
}

// ---------------------------------------------------------------------------
extern "C" void kernel_launch(void* const* d_in, const int* in_sizes, int n_in,
                              void* d_out, int out_size) {
    const float* cross    = (const float*)d_in[0];
    const float* node_emb = (const float*)d_in[1];
    const float* w_ih     = (const float*)d_in[2];
    const float* w_hh     = (const float*)d_in[3];
    const float* b_ih     = (const float*)d_in[4];
    const float* b_hh     = (const float*)d_in[5];
    const int*   paths    = (const int*)d_in[6];
    float* out = (float*)d_out;

    cudaFuncSetAttribute(lstm_mma, cudaFuncAttributeMaxDynamicSharedMemorySize, SMEM_SZ);
    prep_kernel<<<(2*NG*DD + 255)/256, 256>>>(w_ih, w_hh, b_ih, b_hh);
    leaf_kernel<<<(NSEQ*32 + 127)/128, 128>>>(cross, paths);
    dummy_k<<<1, 32>>>();
    dummy_k<<<1, 32>>>();
    dummy_k<<<1, 32>>>();
    lstm_mma<<<NBLK, NTHR, SMEM_SZ>>>(node_emb, out);   // launch #6 -> ncu -s 5
}

// round 12
// speedup vs baseline: 1.3801x; 1.3801x over previous
#include <cuda_runtime.h>
#include <cuda_fp16.h>
#include <cstdint>

#define BB   512
#define TT   100
#define LL   256
#define DD   128
#define PP   9
#define NSEQ (BB*TT)
#define NG   512
#define MROWS 128
#define NCLUST (NSEQ/MROWS)  // 400 clusters -> 800 CTAs
#define NTHR 512
#define ROWB  272            // padded row stride bytes
#define HALFB (256*ROWB)     // 69632: one part (Wih or Whh) for one rank (256 rows)
#define WB2   (2*HALFB)      // 139264: resident W per rank

// SMEM layout (dynamic)
#define SM_W    0            // 139264 resident [Wih_rk | Whh_rk]
#define SM_AX   139264       // 34816 x tile
#define SM_AH   174080       // 34816 h tile (full 128 h-dims)
#define SM_BIAS 208896       // 2048
#define SM_NID  210944       // 4608
#define SM_ACT  215552       // 512
#define SM_MBAR 216064       // 8
#define SMEM_SZ 216192

__device__ __align__(128) unsigned char g_Bimg[2*WB2];   // [rank][part][n][k]
__device__ float g_bias[NG];
__device__ int   g_nids[NSEQ*PP];
__device__ int   g_active[NSEQ];

__device__ __forceinline__ float sigf(float x)   { return 1.0f / (1.0f + __expf(-x)); }
__device__ __forceinline__ float tanhf_(float x) { return 1.0f - 2.0f / (__expf(2.0f*x) + 1.0f); }

__device__ __forceinline__ uint32_t smem_u32(const void* p) {
    uint32_t a;
    asm("{ .reg .u64 t; cvta.to.shared.u64 t, %1; cvt.u32.u64 %0, t; }" : "=r"(a) : "l"(p));
    return a;
}
__device__ __forceinline__ uint32_t cta_rank() {
    uint32_t r; asm("mov.u32 %0, %%cluster_ctarank;" : "=r"(r)); return r;
}
__device__ __forceinline__ void mbar_init(uint32_t mbar, uint32_t cnt) {
    asm volatile("mbarrier.init.shared.b64 [%0], %1;" :: "r"(mbar), "r"(cnt) : "memory");
}
__device__ __forceinline__ void mbar_expect_tx(uint32_t mbar, uint32_t bytes) {
    asm volatile("mbarrier.arrive.expect_tx.shared.b64 _, [%0], %1;" :: "r"(mbar), "r"(bytes) : "memory");
}
__device__ __forceinline__ void mbar_wait(uint32_t mbar, uint32_t ph) {
    asm volatile(
        "{\n\t.reg .pred P;\n\tLW_%=:\n\t"
        "mbarrier.try_wait.parity.acquire.cta.shared::cta.b64 P, [%0], %1, 0x989680;\n\t"
        "@P bra LD_%=;\n\tbra LW_%=;\n\tLD_%=:\n\t}"
        :: "r"(mbar), "r"(ph) : "memory");
}
__device__ __forceinline__ void bulk_g2s(uint32_t dst, const void* src, uint32_t bytes, uint32_t mbar) {
    asm volatile(
        "cp.async.bulk.shared::cluster.global.mbarrier::complete_tx::bytes [%0], [%1], %2, [%3];"
        :: "r"(dst), "l"(src), "r"(bytes), "r"(mbar) : "memory");
}
__device__ __forceinline__ void fence_async() {
    asm volatile("fence.proxy.async.shared::cta;" ::: "memory");
}
__device__ __forceinline__ void cluster_sync() {
    asm volatile("barrier.cluster.arrive.aligned;" ::: "memory");
    asm volatile("barrier.cluster.wait.aligned;" ::: "memory");
}
__device__ __forceinline__ void st_remote_b16(uint32_t laddr, uint32_t peer, uint16_t v) {
    uint32_t r;
    asm volatile("mapa.shared::cluster.u32 %0, %1, %2;" : "=r"(r) : "r"(laddr), "r"(peer));
    asm volatile("st.shared::cluster.b16 [%0], %1;" :: "r"(r), "h"(v) : "memory");
}
__device__ __forceinline__ void mma16816h(float* d, const uint32_t* a, const uint32_t* b) {
    asm volatile(
        "mma.sync.aligned.m16n8k16.row.col.f32.f16.f16.f32 "
        "{%0,%1,%2,%3}, {%4,%5,%6,%7}, {%8,%9}, {%0,%1,%2,%3};"
        : "+f"(d[0]), "+f"(d[1]), "+f"(d[2]), "+f"(d[3])
        : "r"(a[0]), "r"(a[1]), "r"(a[2]), "r"(a[3]), "r"(b[0]), "r"(b[1]));
}
__device__ __forceinline__ void ldsm4(uint32_t* r, uint32_t addr) {
    asm volatile("ldmatrix.sync.aligned.m8n8.x4.shared.b16 {%0,%1,%2,%3}, [%4];"
        : "=r"(r[0]), "=r"(r[1]), "=r"(r[2]), "=r"(r[3]) : "r"(addr));
}

// One [64m x 32n x 128k] warp product-accumulate (fp16).
// abase: A tile base + per-lane ldmatrix offset. W: 256-row part base.
__device__ __forceinline__ void gemm_pass(uint32_t abase, const char* __restrict__ W,
                                          int nw, int g, int tg, float d[4][4][4]) {
#pragma unroll
    for (int k8 = 0; k8 < 8; k8++) {
        uint32_t a[4][4], b[4][2];
#pragma unroll
        for (int mi = 0; mi < 4; mi++)
            ldsm4(a[mi], abase + mi*(16*ROWB) + k8*32);
        const int kb = (k8*16 + tg*2) * 2;
#pragma unroll
        for (int ni = 0; ni < 4; ni++) {
            const char* wr = W + (nw*32 + ni*8 + g)*ROWB + kb;
            b[ni][0] = *(const uint32_t*)wr;
            b[ni][1] = *(const uint32_t*)(wr + 16);
        }
#pragma unroll
        for (int mi = 0; mi < 4; mi++)
#pragma unroll
            for (int ni = 0; ni < 4; ni++)
                mma16816h(d[mi][ni], a[mi], b[ni]);
    }
}

// ---------------------------------------------------------------------------
// prep: per-rank fp16 W image. rank rk owns j in [rk*64,(rk+1)*64).
// row n = j_local*4 + gate (gate-interleaved), 272B rows, part 0=Wih 1=Whh.
// ---------------------------------------------------------------------------
__global__ void prep_kernel(const float* __restrict__ w_ih, const float* __restrict__ w_hh,
                            const float* __restrict__ b_ih, const float* __restrict__ b_hh) {
    int idx = blockIdx.x * blockDim.x + threadIdx.x;
    if (idx < NG) g_bias[idx] = b_ih[idx] + b_hh[idx];
    if (idx >= 2 * NG * DD) return;
    int part = idx >> 16;          // 0: Wih, 1: Whh
    int rem  = idx & 65535;
    int r = rem >> 7;              // gate*128 + j
    int k = rem & 127;
    int gate = r >> 7, j = r & 127;
    int rk = j >> 6, jl = j & 63;
    int n = (jl << 2) | gate;
    float w = (part == 0) ? w_ih[r * DD + k] : w_hh[r * DD + k];
    *(__half*)((char*)g_Bimg + rk*WB2 + part*HALFB + n*ROWB + k*2) = __float2half(w);
}

// ---------------------------------------------------------------------------
__global__ void leaf_kernel(const float* __restrict__ cross, const int* __restrict__ paths) {
    int warp = (blockIdx.x * blockDim.x + threadIdx.x) >> 5;
    int lane = threadIdx.x & 31;
    if (warp >= NSEQ) return;
    int b = warp / TT;
    int t = warp - b * TT;
    const float* row = cross + (size_t)b * (TT*LL) + (size_t)t * LL;
    float bv = -3.0e38f; int bl = 0; int anyp = 0;
#pragma unroll
    for (int i = 0; i < LL/32; i++) {
        int l = lane + 32*i;
        float v = row[l];
        if (v > 0.0f) anyp = 1;
        if (v > bv) { bv = v; bl = l; }
    }
#pragma unroll
    for (int off = 16; off > 0; off >>= 1) {
        float ov = __shfl_down_sync(0xffffffffu, bv, off);
        int   ol = __shfl_down_sync(0xffffffffu, bl, off);
        if (ov > bv || (ov == bv && ol < bl)) { bv = ov; bl = ol; }
    }
    anyp = __any_sync(0xffffffffu, anyp);
    int leaf = __shfl_sync(0xffffffffu, bl, 0);
    if (lane < PP) g_nids[warp*PP + lane] = paths[((size_t)t*LL + leaf)*PP + lane];
    if (lane == 0) g_active[warp] = anyp;
}

// ---------------------------------------------------------------------------
// Cluster LSTM: 2 CTAs per cluster; rank rk computes gate cols for its j-half
// with W fully SMEM-resident; h halves exchanged via DSMEM each step.
// ---------------------------------------------------------------------------
__global__ void __launch_bounds__(NTHR, 1) __cluster_dims__(2, 1, 1)
lstm_mma(const float* __restrict__ node_emb, float* __restrict__ out) {
    extern __shared__ __align__(16) char smem[];
    const uint32_t sb = smem_u32(smem);
    const int tid  = threadIdx.x;
    const int wid  = tid >> 5, lane = tid & 31;
    const int g    = lane >> 2, tg = lane & 3;
    const int mw   = wid >> 3, nw = wid & 7;        // 2m x 8n warp grid
    const uint32_t rk = cta_rank();
    const uint32_t peer = rk ^ 1u;
    const int cid  = blockIdx.x >> 1;
    const int bt0  = cid * MROWS;

    // resident W load (once)
    if (tid == 0) {
        mbar_init(sb + SM_MBAR, 1);
        fence_async();
        mbar_expect_tx(sb + SM_MBAR, WB2);
        bulk_g2s(sb + SM_W, (const char*)g_Bimg + (size_t)rk*WB2, WB2, sb + SM_MBAR);
    }
    int* snid   = (int*)(smem + SM_NID);
    int* sact   = (int*)(smem + SM_ACT);
    float* sbias = (float*)(smem + SM_BIAS);
    for (int i = tid; i < MROWS*PP; i += NTHR) snid[i] = g_nids[bt0*PP + i];
    for (int i = tid; i < MROWS; i += NTHR)    sact[i] = g_active[bt0 + i];
    for (int i = tid; i < NG; i += NTHR)       sbias[i] = g_bias[i];
    __syncthreads();

    const uint32_t lrow = lane & 15;
    const uint32_t lcol = (lane & 16) ? 16u : 0u;
    const uint32_t aoff = (mw*64 + lrow) * ROWB + lcol;
    const uint32_t ax_b = sb + SM_AX + aoff;
    const uint32_t ah_b = sb + SM_AH + aoff;

    const int rbase = mw*64 + g + ((tg & 1) ? 8 : 0);   // epilogue row base

    float creg[16];
#pragma unroll
    for (int i = 0; i < 16; i++) creg[i] = 0.0f;

    bool wready = false;

    for (int p = 0; p < PP; p++) {
        // ---- gather x_p into A_x (fp16) ----
#pragma unroll
        for (int i = 0; i < 8; i++) {
            int idx = i * NTHR + tid;          // 4096 float4 items
            int mm = idx >> 5, kq = (idx & 31) << 2;
            const float4 v = *(const float4*)(node_emb + (size_t)snid[mm*PP + p]*DD + kq);
            __half2 a = __floats2half2_rn(v.x, v.y);
            __half2 b = __floats2half2_rn(v.z, v.w);
            uint2 pk; pk.x = *(uint32_t*)&a; pk.y = *(uint32_t*)&b;
            *(uint2*)(smem + SM_AX + mm*ROWB + kq*2) = pk;
        }
        __syncthreads();   // x visible (and, via last cluster_sync, h from p-1)
        if (!wready) { mbar_wait(sb + SM_MBAR, 0); wready = true; }

        float d[4][4][4];
#pragma unroll
        for (int mi = 0; mi < 4; mi++)
#pragma unroll
            for (int ni = 0; ni < 4; ni++)
#pragma unroll
                for (int e = 0; e < 4; e++) d[mi][ni][e] = 0.0f;

        gemm_pass(ax_b, smem + SM_W, nw, g, tg, d);               // x @ Wih_rk
        if (p > 0)
            gemm_pass(ah_b, smem + SM_W + HALFB, nw, g, tg, d);   // h @ Whh_rk

        cluster_sync();   // all A_h reads complete cluster-wide

        // ---- epilogue: gates -> c, h; write h to local + peer A_h ----
#pragma unroll
        for (int ni = 0; ni < 4; ni++) {
            const int jg = (int)rk*64 + nw*8 + ni*2 + (tg >> 1);
            const float bi = sbias[jg],       bfv = sbias[128 + jg];
            const float bg = sbias[256 + jg], bo  = sbias[384 + jg];
#pragma unroll
            for (int mi = 0; mi < 4; mi++) {
                float d0 = d[mi][ni][0], d1 = d[mi][ni][1];
                float d2 = d[mi][ni][2], d3 = d[mi][ni][3];
                float s0 = __shfl_xor_sync(0xffffffffu, d0, 1);
                float s1 = __shfl_xor_sync(0xffffffffu, d1, 1);
                float s2 = __shfl_xor_sync(0xffffffffu, d2, 1);
                float s3 = __shfl_xor_sync(0xffffffffu, d3, 1);
                float gi, gf, gg, go;
                if ((tg & 1) == 0) { gi = d0; gf = d1; gg = s0; go = s1; }
                else               { gi = s2; gf = s3; gg = d2; go = d3; }
                float& cc = creg[mi*4 + ni];
                cc = sigf(gf + bfv) * cc + sigf(gi + bi) * tanhf_(gg + bg);
                float h = sigf(go + bo) * tanhf_(cc);
                const int r = rbase + mi*16;
                if (p < PP - 1) {
                    uint32_t la = sb + SM_AH + r*ROWB + jg*2;
                    __half hh = __float2half(h);
                    *(__half*)(smem + SM_AH + r*ROWB + jg*2) = hh;
                    st_remote_b16(la, peer, *(uint16_t*)&hh);
                } else {
                    out[(size_t)(bt0 + r)*DD + jg] = sact[r] ? h : 0.0f;
                }
            }
        }

        if (p < PP - 1) cluster_sync();   // h writes (incl. DSMEM) visible
    }
}

// ---------------------------------------------------------------------------
extern "C" void kernel_launch(void* const* d_in, const int* in_sizes, int n_in,
                              void* d_out, int out_size) {
    const float* cross    = (const float*)d_in[0];
    const float* node_emb = (const float*)d_in[1];
    const float* w_ih     = (const float*)d_in[2];
    const float* w_hh     = (const float*)d_in[3];
    const float* b_ih     = (const float*)d_in[4];
    const float* b_hh     = (const float*)d_in[5];
    const int*   paths    = (const int*)d_in[6];
    float* out = (float*)d_out;

    cudaFuncSetAttribute(lstm_mma, cudaFuncAttributeMaxDynamicSharedMemorySize, SMEM_SZ);
    prep_kernel<<<(2*NG*DD + 255)/256, 256>>>(w_ih, w_hh, b_ih, b_hh);
    leaf_kernel<<<(NSEQ*32 + 127)/128, 128>>>(cross, paths);
    lstm_mma<<<2*NCLUST, NTHR, SMEM_SZ>>>(node_emb, out);
}

// round 13
// speedup vs baseline: 1.9923x; 1.4436x over previous
#include <cuda_runtime.h>
#include <cuda_fp16.h>
#include <cstdint>

#define BB   512
#define TT   100
#define LL   256
#define DD   128
#define PP   9
#define NSEQ (BB*TT)
#define NG   512
#define NTOT (TT*(2*LL-1))   // 51100 nodes
#define ROWB  272            // padded row stride bytes
#define HALFB (256*ROWB)     // 69632: one part for one rank (256 gate-rows)
#define WB2   (2*HALFB)      // per-rank [Wih | Whh]

// ---- prep image (same layout as R12): [rank][part][n_local][k] fp16 ----
__device__ __align__(128) unsigned char g_Bimg[2*WB2];
__device__ float g_bias[NG];
__device__ int   g_nids[NSEQ*PP];
__device__ int   g_active[NSEQ];
// per-node gate table, fragment-permuted fp16: row = node (1024 B),
// byte = node*1024 + b32*64 + tg*16, halves[2*ni+e] for col n = b32*32+ni*8+2tg+e
__device__ __align__(128) unsigned char g_gn[(size_t)NTOT*1024];

// ---- gnode kernel SMEM ----
#define SA_W0   0            // 69632 Wih rank0 (cols 0..255)
#define SA_W1   69632        // 69632 Wih rank1 (cols 256..511)
#define SA_X    139264       // 34816 x tile (128 rows)
#define SA_BIAS 174080       // 2048
#define SA_MBAR 176128
#define SMEM_A  176256

// ---- LSTM kernel SMEM ----
#define SL_W    0            // 69632 Whh half (rank's 256 gate-rows)
#define SL_AH   69632        // 17408 h tile (64 rows x ROWB, full 128 j)
#define SL_NID  87040        // 2304 (64*9 ints)
#define SL_ACT  89344        // 256
#define SL_MBAR 89600        // 8
#define SMEM_L  89728        // -> 2 CTAs/SM

__device__ __forceinline__ float sigf(float x)   { return 1.0f / (1.0f + __expf(-x)); }
__device__ __forceinline__ float tanhf_(float x) { return 1.0f - 2.0f / (__expf(2.0f*x) + 1.0f); }

__device__ __forceinline__ uint32_t smem_u32(const void* p) {
    uint32_t a;
    asm("{ .reg .u64 t; cvta.to.shared.u64 t, %1; cvt.u32.u64 %0, t; }" : "=r"(a) : "l"(p));
    return a;
}
__device__ __forceinline__ uint32_t cta_rank() {
    uint32_t r; asm("mov.u32 %0, %%cluster_ctarank;" : "=r"(r)); return r;
}
__device__ __forceinline__ void mbar_init(uint32_t mbar, uint32_t cnt) {
    asm volatile("mbarrier.init.shared.b64 [%0], %1;" :: "r"(mbar), "r"(cnt) : "memory");
}
__device__ __forceinline__ void mbar_expect_tx(uint32_t mbar, uint32_t bytes) {
    asm volatile("mbarrier.arrive.expect_tx.shared.b64 _, [%0], %1;" :: "r"(mbar), "r"(bytes) : "memory");
}
__device__ __forceinline__ void mbar_wait(uint32_t mbar, uint32_t ph) {
    asm volatile(
        "{\n\t.reg .pred P;\n\tLW_%=:\n\t"
        "mbarrier.try_wait.parity.acquire.cta.shared::cta.b64 P, [%0], %1, 0x989680;\n\t"
        "@P bra LD_%=;\n\tbra LW_%=;\n\tLD_%=:\n\t}"
        :: "r"(mbar), "r"(ph) : "memory");
}
__device__ __forceinline__ void bulk_g2s(uint32_t dst, const void* src, uint32_t bytes, uint32_t mbar) {
    asm volatile(
        "cp.async.bulk.shared::cluster.global.mbarrier::complete_tx::bytes [%0], [%1], %2, [%3];"
        :: "r"(dst), "l"(src), "r"(bytes), "r"(mbar) : "memory");
}
__device__ __forceinline__ void fence_async() {
    asm volatile("fence.proxy.async.shared::cta;" ::: "memory");
}
__device__ __forceinline__ void cluster_sync() {
    asm volatile("barrier.cluster.arrive.aligned;" ::: "memory");
    asm volatile("barrier.cluster.wait.aligned;" ::: "memory");
}
__device__ __forceinline__ void st_remote_b16(uint32_t laddr, uint32_t peer, uint16_t v) {
    uint32_t r;
    asm volatile("mapa.shared::cluster.u32 %0, %1, %2;" : "=r"(r) : "r"(laddr), "r"(peer));
    asm volatile("st.shared::cluster.b16 [%0], %1;" :: "r"(r), "h"(v) : "memory");
}
__device__ __forceinline__ void mma16816h(float* d, const uint32_t* a, const uint32_t* b) {
    asm volatile(
        "mma.sync.aligned.m16n8k16.row.col.f32.f16.f16.f32 "
        "{%0,%1,%2,%3}, {%4,%5,%6,%7}, {%8,%9}, {%0,%1,%2,%3};"
        : "+f"(d[0]), "+f"(d[1]), "+f"(d[2]), "+f"(d[3])
        : "r"(a[0]), "r"(a[1]), "r"(a[2]), "r"(a[3]), "r"(b[0]), "r"(b[1]));
}
__device__ __forceinline__ void ldsm4(uint32_t* r, uint32_t addr) {
    asm volatile("ldmatrix.sync.aligned.m8n8.x4.shared.b16 {%0,%1,%2,%3}, [%4];"
        : "=r"(r[0]), "=r"(r[1]), "=r"(r[2]), "=r"(r[3]) : "r"(addr));
}

// One [64m x 32n x 128k] warp product-accumulate (fp16).
// abase: A tile base + per-lane ldmatrix offset. B row = nw*32 + ni*8 + g.
__device__ __forceinline__ void gemm_pass(uint32_t abase, const char* __restrict__ W,
                                          int nw, int g, int tg, float d[4][4][4]) {
#pragma unroll
    for (int k8 = 0; k8 < 8; k8++) {
        uint32_t a[4][4], b[4][2];
#pragma unroll
        for (int mi = 0; mi < 4; mi++)
            ldsm4(a[mi], abase + mi*(16*ROWB) + k8*32);
        const int kb = (k8*16 + tg*2) * 2;
#pragma unroll
        for (int ni = 0; ni < 4; ni++) {
            const char* wr = W + (nw*32 + ni*8 + g)*ROWB + kb;
            b[ni][0] = *(const uint32_t*)wr;
            b[ni][1] = *(const uint32_t*)(wr + 16);
        }
#pragma unroll
        for (int mi = 0; mi < 4; mi++)
#pragma unroll
            for (int ni = 0; ni < 4; ni++)
                mma16816h(d[mi][ni], a[mi], b[ni]);
    }
}

// ---------------------------------------------------------------------------
// prep (R12 layout): rank rk owns j in [rk*64,(rk+1)*64); row n = jl*4+gate.
// ---------------------------------------------------------------------------
__global__ void prep_kernel(const float* __restrict__ w_ih, const float* __restrict__ w_hh,
                            const float* __restrict__ b_ih, const float* __restrict__ b_hh) {
    int idx = blockIdx.x * blockDim.x + threadIdx.x;
    if (idx < NG) g_bias[idx] = b_ih[idx] + b_hh[idx];
    if (idx >= 2 * NG * DD) return;
    int part = idx >> 16;          // 0: Wih, 1: Whh
    int rem  = idx & 65535;
    int r = rem >> 7;              // gate*128 + j
    int k = rem & 127;
    int gate = r >> 7, j = r & 127;
    int rk = j >> 6, jl = j & 63;
    int n = (jl << 2) | gate;
    float w = (part == 0) ? w_ih[r * DD + k] : w_hh[r * DD + k];
    *(__half*)((char*)g_Bimg + rk*WB2 + part*HALFB + n*ROWB + k*2) = __float2half(w);
}

// ---------------------------------------------------------------------------
__global__ void leaf_kernel(const float* __restrict__ cross, const int* __restrict__ paths) {
    int warp = (blockIdx.x * blockDim.x + threadIdx.x) >> 5;
    int lane = threadIdx.x & 31;
    if (warp >= NSEQ) return;
    int b = warp / TT;
    int t = warp - b * TT;
    const float* row = cross + (size_t)b * (TT*LL) + (size_t)t * LL;
    float bv = -3.0e38f; int bl = 0; int anyp = 0;
#pragma unroll
    for (int i = 0; i < LL/32; i++) {
        int l = lane + 32*i;
        float v = row[l];
        if (v > 0.0f) anyp = 1;
        if (v > bv) { bv = v; bl = l; }
    }
#pragma unroll
    for (int off = 16; off > 0; off >>= 1) {
        float ov = __shfl_down_sync(0xffffffffu, bv, off);
        int   ol = __shfl_down_sync(0xffffffffu, bl, off);
        if (ov > bv || (ov == bv && ol < bl)) { bv = ov; bl = ol; }
    }
    anyp = __any_sync(0xffffffffu, anyp);
    int leaf = __shfl_sync(0xffffffffu, bl, 0);
    if (lane < PP) g_nids[warp*PP + lane] = paths[((size_t)t*LL + leaf)*PP + lane];
    if (lane == 0) g_active[warp] = anyp;
}

// ---------------------------------------------------------------------------
// gnode: gnode[node] = node_emb[node] @ Wih^T + bias (fp16, fragment-permuted)
// grid 400 x 128 node rows; 256 thr, warp grid 2mw x 4nw, 4 col-quarters.
// ---------------------------------------------------------------------------
__global__ void __launch_bounds__(256, 1)
gnode_kernel(const float* __restrict__ node_emb) {
    extern __shared__ __align__(16) char smem[];
    const uint32_t sb = smem_u32(smem);
    const int tid  = threadIdx.x;
    const int wid  = tid >> 5, lane = tid & 31;
    const int g    = lane >> 2, tg = lane & 3;
    const int mw   = wid >> 2, nw = wid & 3;
    const int row0 = blockIdx.x * 128;

    if (tid == 0) {
        mbar_init(sb + SA_MBAR, 1);
        fence_async();
        mbar_expect_tx(sb + SA_MBAR, 2*HALFB);
        bulk_g2s(sb + SA_W0, (const char*)g_Bimg,       HALFB, sb + SA_MBAR);  // rank0 Wih
        bulk_g2s(sb + SA_W1, (const char*)g_Bimg + WB2, HALFB, sb + SA_MBAR);  // rank1 Wih
    }
    float* sbias = (float*)(smem + SA_BIAS);
    for (int i = tid; i < NG; i += 256) sbias[i] = g_bias[i];

    // x tile: 128 node rows (clamped) -> fp16
#pragma unroll
    for (int i = 0; i < 16; i++) {
        int idx = i * 256 + tid;             // 4096 float4 items
        int mm = idx >> 5, kq = (idx & 31) << 2;
        int gr = row0 + mm; if (gr >= NTOT) gr = NTOT - 1;
        const float4 v = *(const float4*)(node_emb + (size_t)gr*DD + kq);
        __half2 a = __floats2half2_rn(v.x, v.y);
        __half2 b = __floats2half2_rn(v.z, v.w);
        uint2 pk; pk.x = *(uint32_t*)&a; pk.y = *(uint32_t*)&b;
        *(uint2*)(smem + SA_X + mm*ROWB + kq*2) = pk;
    }
    mbar_wait(sb + SA_MBAR, 0);
    __syncthreads();

    const uint32_t abase = sb + SA_X + (mw*64 + (lane & 15))*ROWB + ((lane & 16) ? 16u : 0u);
    const int g0 = (2*tg)     & 3;
    const int g1 = (2*tg + 1) & 3;

#pragma unroll
    for (int q4 = 0; q4 < 4; q4++) {
        const char* W = smem + ((q4 >= 2) ? SA_W1 : SA_W0) + (q4 & 1)*(128*ROWB);
        float d[4][4][4];
#pragma unroll
        for (int mi = 0; mi < 4; mi++)
#pragma unroll
            for (int ni = 0; ni < 4; ni++)
#pragma unroll
                for (int e = 0; e < 4; e++) d[mi][ni][e] = 0.0f;
        gemm_pass(abase, W, nw, g, tg, d);

        uint32_t lo2[4][4], hi2[4][4];
#pragma unroll
        for (int ni = 0; ni < 4; ni++) {
            const int j = q4*32 + nw*8 + ni*2 + (tg >> 1);
            const float b0 = sbias[g0*128 + j];
            const float b1 = sbias[g1*128 + j];
#pragma unroll
            for (int mi = 0; mi < 4; mi++) {
                __half2 a = __floats2half2_rn(d[mi][ni][0] + b0, d[mi][ni][1] + b1);
                __half2 b = __floats2half2_rn(d[mi][ni][2] + b0, d[mi][ni][3] + b1);
                lo2[mi][ni] = *(uint32_t*)&a;
                hi2[mi][ni] = *(uint32_t*)&b;
            }
        }
        const uint32_t coff = (q4*4 + nw)*64 + tg*16;
#pragma unroll
        for (int mi = 0; mi < 4; mi++) {
            int rlo = row0 + mw*64 + mi*16 + g;
            int rhi = rlo + 8;
            if (rlo < NTOT)
                *(uint4*)(g_gn + (size_t)rlo*1024 + coff) =
                    make_uint4(lo2[mi][0], lo2[mi][1], lo2[mi][2], lo2[mi][3]);
            if (rhi < NTOT)
                *(uint4*)(g_gn + (size_t)rhi*1024 + coff) =
                    make_uint4(hi2[mi][0], hi2[mi][1], hi2[mi][2], hi2[mi][3]);
        }
    }
}

// ---------------------------------------------------------------------------
// LSTM: 2-CTA cluster (j-split), CTA = 64 seqs, 256 thr, 2 CTAs/SM.
// Accumulators initialized from gnode (L2-resident); only h-GEMM per step.
// ---------------------------------------------------------------------------
__global__ void __launch_bounds__(256, 2) __cluster_dims__(2, 1, 1)
lstm_mma(float* __restrict__ out) {
    extern __shared__ __align__(16) char smem[];
    const uint32_t sb = smem_u32(smem);
    const int tid  = threadIdx.x;
    const int wid  = tid >> 5, lane = tid & 31;
    const int g    = lane >> 2, tg = lane & 3;
    const int nw   = wid;                     // 1m x 8n warp grid
    const uint32_t rk = cta_rank();
    const uint32_t peer = rk ^ 1u;
    const int cid  = blockIdx.x >> 1;
    const int bt0  = cid * 64;

    if (tid == 0) {
        mbar_init(sb + SL_MBAR, 1);
        fence_async();
        mbar_expect_tx(sb + SL_MBAR, HALFB);
        bulk_g2s(sb + SL_W, (const char*)g_Bimg + (size_t)rk*WB2 + HALFB, HALFB, sb + SL_MBAR);
    }
    int* snid = (int*)(smem + SL_NID);
    int* sact = (int*)(smem + SL_ACT);
    for (int i = tid; i < 64*PP; i += 256) snid[i] = g_nids[bt0*PP + i];
    if (tid < 64) sact[tid] = g_active[bt0 + tid];
    __syncthreads();

    const uint32_t abase = sb + SL_AH + (lane & 15)*ROWB + ((lane & 16) ? 16u : 0u);
    const int rbase = g + ((tg & 1) ? 8 : 0);
    const unsigned char* gbase = g_gn + rk*512 + nw*64 + tg*16;

    float creg[16];
#pragma unroll
    for (int i = 0; i < 16; i++) creg[i] = 0.0f;

    bool wready = false;

    for (int p = 0; p < PP; p++) {
        // ---- init d from gnode (fragment-permuted; coalesced LDG.128) ----
        uint4 fr[8];
#pragma unroll
        for (int mi = 0; mi < 4; mi++) {
            const int rlo = mi*16 + g, rhi = rlo + 8;
            fr[2*mi]   = *(const uint4*)(gbase + (size_t)snid[rlo*PP + p]*1024);
            fr[2*mi+1] = *(const uint4*)(gbase + (size_t)snid[rhi*PP + p]*1024);
        }
        float d[4][4][4];
#pragma unroll
        for (int mi = 0; mi < 4; mi++) {
            const uint32_t* lo = (const uint32_t*)&fr[2*mi];
            const uint32_t* hi = (const uint32_t*)&fr[2*mi+1];
#pragma unroll
            for (int ni = 0; ni < 4; ni++) {
                float2 vlo = __half22float2(*(const __half2*)&lo[ni]);
                float2 vhi = __half22float2(*(const __half2*)&hi[ni]);
                d[mi][ni][0] = vlo.x; d[mi][ni][1] = vlo.y;
                d[mi][ni][2] = vhi.x; d[mi][ni][3] = vhi.y;
            }
        }

        if (p > 0) {
            if (!wready) { mbar_wait(sb + SL_MBAR, 0); wready = true; }
            gemm_pass(abase, smem + SL_W, nw, g, tg, d);   // h @ Whh_rk
            cluster_sync();   // all A_h reads complete cluster-wide
        }

        // ---- epilogue: gates -> c, h; write h local + peer via DSMEM ----
#pragma unroll
        for (int ni = 0; ni < 4; ni++) {
            const int jg = (int)rk*64 + nw*8 + ni*2 + (tg >> 1);
#pragma unroll
            for (int mi = 0; mi < 4; mi++) {
                float d0 = d[mi][ni][0], d1 = d[mi][ni][1];
                float d2 = d[mi][ni][2], d3 = d[mi][ni][3];
                float s0 = __shfl_xor_sync(0xffffffffu, d0, 1);
                float s1 = __shfl_xor_sync(0xffffffffu, d1, 1);
                float s2 = __shfl_xor_sync(0xffffffffu, d2, 1);
                float s3 = __shfl_xor_sync(0xffffffffu, d3, 1);
                float gi, gf, gg, go;
                if ((tg & 1) == 0) { gi = d0; gf = d1; gg = s0; go = s1; }
                else               { gi = s2; gf = s3; gg = d2; go = d3; }
                float& cc = creg[mi*4 + ni];
                cc = sigf(gf) * cc + sigf(gi) * tanhf_(gg);
                float h = sigf(go) * tanhf_(cc);
                const int r = rbase + mi*16;
                if (p < PP - 1) {
                    uint32_t la = sb + SL_AH + r*ROWB + jg*2;
                    __half hh = __float2half(h);
                    *(__half*)(smem + SL_AH + r*ROWB + jg*2) = hh;
                    st_remote_b16(la, peer, *(uint16_t*)&hh);
                } else {
                    out[(size_t)(bt0 + r)*DD + jg] = sact[r] ? h : 0.0f;
                }
            }
        }

        if (p < PP - 1) cluster_sync();   // h writes (incl. DSMEM) visible
    }
}

// ---------------------------------------------------------------------------
extern "C" void kernel_launch(void* const* d_in, const int* in_sizes, int n_in,
                              void* d_out, int out_size) {
    const float* cross    = (const float*)d_in[0];
    const float* node_emb = (const float*)d_in[1];
    const float* w_ih     = (const float*)d_in[2];
    const float* w_hh     = (const float*)d_in[3];
    const float* b_ih     = (const float*)d_in[4];
    const float* b_hh     = (const float*)d_in[5];
    const int*   paths    = (const int*)d_in[6];
    float* out = (float*)d_out;

    cudaFuncSetAttribute(gnode_kernel, cudaFuncAttributeMaxDynamicSharedMemorySize, SMEM_A);
    cudaFuncSetAttribute(lstm_mma, cudaFuncAttributeMaxDynamicSharedMemorySize, SMEM_L);

    prep_kernel<<<(2*NG*DD + 255)/256, 256>>>(w_ih, w_hh, b_ih, b_hh);
    leaf_kernel<<<(NSEQ*32 + 127)/128, 128>>>(cross, paths);
    gnode_kernel<<<(NTOT + 127)/128, 256, SMEM_A>>>(node_emb);
    lstm_mma<<<2*(NSEQ/64), 256, SMEM_L>>>(out);
}

// round 14
// speedup vs baseline: 2.0421x; 1.0250x over previous
#include <cuda_runtime.h>
#include <cuda_fp16.h>
#include <cstdint>

#define BB   512
#define TT   100
#define LL   256
#define DD   128
#define PP   9
#define NSEQ (BB*TT)
#define NG   512
#define NTOT (TT*(2*LL-1))   // 51100 nodes
#define ROWB  272            // padded row stride bytes
#define HALFB (256*ROWB)     // 69632: one part for one rank (256 gate-rows)
#define WB2   (2*HALFB)      // per-rank [Wih | Whh]

// ---- prep image (R12/R13 layout, validated): [rank][part][n_local][k] fp16 ----
__device__ __align__(128) unsigned char g_Bimg[2*WB2];
__device__ float g_bias[NG];
__device__ int   g_nids[NSEQ*PP];
__device__ int   g_active[NSEQ];
// per-node gate table, fragment-permuted fp16 (R13-validated):
// byte = node*1024 + b32*64 + tg*16; uint4 = 4 half2 cols n=b32*32+ni*8+2tg{,+1}
__device__ __align__(128) unsigned char g_gn[(size_t)NTOT*1024];

// ---- gnode kernel SMEM ----
#define SA_W0   0            // 69632 Wih rank0 (cols 0..255)
#define SA_W1   69632        // 69632 Wih rank1 (cols 256..511)
#define SA_X    139264       // 34816 x tile (128 rows)
#define SA_BIAS 174080       // 2048
#define SA_MBAR 176128
#define SMEM_A  176256

// ---- LSTM kernel SMEM (single CTA, no cluster) ----
#define SL_W    0            // 139264 Whh resident (512 gate-rows, both halves)
#define SL_AH0  139264       // 17408 h tile buf0 (64 rows x ROWB)
#define SL_AH1  156672       // 17408 h tile buf1
#define SL_NID  174080       // 2304 (64*9 ints)
#define SL_ACT  176384       // 256
#define SL_MBAR 176640       // 8
#define SMEM_L  176768       // 1 CTA/SM

__device__ __forceinline__ float sigf(float x)   { return 1.0f / (1.0f + __expf(-x)); }
__device__ __forceinline__ float tanhf_(float x) { return 1.0f - 2.0f / (__expf(2.0f*x) + 1.0f); }

__device__ __forceinline__ uint32_t smem_u32(const void* p) {
    uint32_t a;
    asm("{ .reg .u64 t; cvta.to.shared.u64 t, %1; cvt.u32.u64 %0, t; }" : "=r"(a) : "l"(p));
    return a;
}
__device__ __forceinline__ void mbar_init(uint32_t mbar, uint32_t cnt) {
    asm volatile("mbarrier.init.shared.b64 [%0], %1;" :: "r"(mbar), "r"(cnt) : "memory");
}
__device__ __forceinline__ void mbar_expect_tx(uint32_t mbar, uint32_t bytes) {
    asm volatile("mbarrier.arrive.expect_tx.shared.b64 _, [%0], %1;" :: "r"(mbar), "r"(bytes) : "memory");
}
__device__ __forceinline__ void mbar_wait(uint32_t mbar, uint32_t ph) {
    asm volatile(
        "{\n\t.reg .pred P;\n\tLW_%=:\n\t"
        "mbarrier.try_wait.parity.acquire.cta.shared::cta.b64 P, [%0], %1, 0x989680;\n\t"
        "@P bra LD_%=;\n\tbra LW_%=;\n\tLD_%=:\n\t}"
        :: "r"(mbar), "r"(ph) : "memory");
}
__device__ __forceinline__ void bulk_g2s(uint32_t dst, const void* src, uint32_t bytes, uint32_t mbar) {
    asm volatile(
        "cp.async.bulk.shared::cluster.global.mbarrier::complete_tx::bytes [%0], [%1], %2, [%3];"
        :: "r"(dst), "l"(src), "r"(bytes), "r"(mbar) : "memory");
}
__device__ __forceinline__ void fence_async() {
    asm volatile("fence.proxy.async.shared::cta;" ::: "memory");
}
__device__ __forceinline__ void mma16816h(float* d, const uint32_t* a, const uint32_t* b) {
    asm volatile(
        "mma.sync.aligned.m16n8k16.row.col.f32.f16.f16.f32 "
        "{%0,%1,%2,%3}, {%4,%5,%6,%7}, {%8,%9}, {%0,%1,%2,%3};"
        : "+f"(d[0]), "+f"(d[1]), "+f"(d[2]), "+f"(d[3])
        : "r"(a[0]), "r"(a[1]), "r"(a[2]), "r"(a[3]), "r"(b[0]), "r"(b[1]));
}
__device__ __forceinline__ void ldsm4(uint32_t* r, uint32_t addr) {
    asm volatile("ldmatrix.sync.aligned.m8n8.x4.shared.b16 {%0,%1,%2,%3}, [%4];"
        : "=r"(r[0]), "=r"(r[1]), "=r"(r[2]), "=r"(r[3]) : "r"(addr));
}

// One [64m x 32n x 128k] warp product-accumulate (fp16).
// abase: A tile base + per-lane ldmatrix offset. B row = nw*32 + ni*8 + g.
__device__ __forceinline__ void gemm_pass(uint32_t abase, const char* __restrict__ W,
                                          int nw, int g, int tg, float d[4][4][4]) {
#pragma unroll
    for (int k8 = 0; k8 < 8; k8++) {
        uint32_t a[4][4], b[4][2];
#pragma unroll
        for (int mi = 0; mi < 4; mi++)
            ldsm4(a[mi], abase + mi*(16*ROWB) + k8*32);
        const int kb = (k8*16 + tg*2) * 2;
#pragma unroll
        for (int ni = 0; ni < 4; ni++) {
            const char* wr = W + (nw*32 + ni*8 + g)*ROWB + kb;
            b[ni][0] = *(const uint32_t*)wr;
            b[ni][1] = *(const uint32_t*)(wr + 16);
        }
#pragma unroll
        for (int mi = 0; mi < 4; mi++)
#pragma unroll
            for (int ni = 0; ni < 4; ni++)
                mma16816h(d[mi][ni], a[mi], b[ni]);
    }
}

// ---------------------------------------------------------------------------
// prep (R12 layout): rank rk owns j in [rk*64,(rk+1)*64); row n = jl*4+gate.
// ---------------------------------------------------------------------------
__global__ void prep_kernel(const float* __restrict__ w_ih, const float* __restrict__ w_hh,
                            const float* __restrict__ b_ih, const float* __restrict__ b_hh) {
    int idx = blockIdx.x * blockDim.x + threadIdx.x;
    if (idx < NG) g_bias[idx] = b_ih[idx] + b_hh[idx];
    if (idx >= 2 * NG * DD) return;
    int part = idx >> 16;          // 0: Wih, 1: Whh
    int rem  = idx & 65535;
    int r = rem >> 7;              // gate*128 + j
    int k = rem & 127;
    int gate = r >> 7, j = r & 127;
    int rk = j >> 6, jl = j & 63;
    int n = (jl << 2) | gate;
    float w = (part == 0) ? w_ih[r * DD + k] : w_hh[r * DD + k];
    *(__half*)((char*)g_Bimg + rk*WB2 + part*HALFB + n*ROWB + k*2) = __float2half(w);
}

// ---------------------------------------------------------------------------
__global__ void leaf_kernel(const float* __restrict__ cross, const int* __restrict__ paths) {
    int warp = (blockIdx.x * blockDim.x + threadIdx.x) >> 5;
    int lane = threadIdx.x & 31;
    if (warp >= NSEQ) return;
    int b = warp / TT;
    int t = warp - b * TT;
    const float* row = cross + (size_t)b * (TT*LL) + (size_t)t * LL;
    float bv = -3.0e38f; int bl = 0; int anyp = 0;
#pragma unroll
    for (int i = 0; i < LL/32; i++) {
        int l = lane + 32*i;
        float v = row[l];
        if (v > 0.0f) anyp = 1;
        if (v > bv) { bv = v; bl = l; }
    }
#pragma unroll
    for (int off = 16; off > 0; off >>= 1) {
        float ov = __shfl_down_sync(0xffffffffu, bv, off);
        int   ol = __shfl_down_sync(0xffffffffu, bl, off);
        if (ov > bv || (ov == bv && ol < bl)) { bv = ov; bl = ol; }
    }
    anyp = __any_sync(0xffffffffu, anyp);
    int leaf = __shfl_sync(0xffffffffu, bl, 0);
    if (lane < PP) g_nids[warp*PP + lane] = paths[((size_t)t*LL + leaf)*PP + lane];
    if (lane == 0) g_active[warp] = anyp;
}

// ---------------------------------------------------------------------------
// gnode: gnode[node] = node_emb[node] @ Wih^T + bias (fp16, fragment-permuted)
// (unchanged from R13 — validated)
// ---------------------------------------------------------------------------
__global__ void __launch_bounds__(256, 1)
gnode_kernel(const float* __restrict__ node_emb) {
    extern __shared__ __align__(16) char smem[];
    const uint32_t sb = smem_u32(smem);
    const int tid  = threadIdx.x;
    const int wid  = tid >> 5, lane = tid & 31;
    const int g    = lane >> 2, tg = lane & 3;
    const int mw   = wid >> 2, nw = wid & 3;
    const int row0 = blockIdx.x * 128;

    if (tid == 0) {
        mbar_init(sb + SA_MBAR, 1);
        fence_async();
        mbar_expect_tx(sb + SA_MBAR, 2*HALFB);
        bulk_g2s(sb + SA_W0, (const char*)g_Bimg,       HALFB, sb + SA_MBAR);
        bulk_g2s(sb + SA_W1, (const char*)g_Bimg + WB2, HALFB, sb + SA_MBAR);
    }
    float* sbias = (float*)(smem + SA_BIAS);
    for (int i = tid; i < NG; i += 256) sbias[i] = g_bias[i];

#pragma unroll
    for (int i = 0; i < 16; i++) {
        int idx = i * 256 + tid;
        int mm = idx >> 5, kq = (idx & 31) << 2;
        int gr = row0 + mm; if (gr >= NTOT) gr = NTOT - 1;
        const float4 v = *(const float4*)(node_emb + (size_t)gr*DD + kq);
        __half2 a = __floats2half2_rn(v.x, v.y);
        __half2 b = __floats2half2_rn(v.z, v.w);
        uint2 pk; pk.x = *(uint32_t*)&a; pk.y = *(uint32_t*)&b;
        *(uint2*)(smem + SA_X + mm*ROWB + kq*2) = pk;
    }
    mbar_wait(sb + SA_MBAR, 0);
    __syncthreads();

    const uint32_t abase = sb + SA_X + (mw*64 + (lane & 15))*ROWB + ((lane & 16) ? 16u : 0u);
    const int g0 = (2*tg)     & 3;
    const int g1 = (2*tg + 1) & 3;

#pragma unroll
    for (int q4 = 0; q4 < 4; q4++) {
        const char* W = smem + ((q4 >= 2) ? SA_W1 : SA_W0) + (q4 & 1)*(128*ROWB);
        float d[4][4][4];
#pragma unroll
        for (int mi = 0; mi < 4; mi++)
#pragma unroll
            for (int ni = 0; ni < 4; ni++)
#pragma unroll
                for (int e = 0; e < 4; e++) d[mi][ni][e] = 0.0f;
        gemm_pass(abase, W, nw, g, tg, d);

        uint32_t lo2[4][4], hi2[4][4];
#pragma unroll
        for (int ni = 0; ni < 4; ni++) {
            const int j = q4*32 + nw*8 + ni*2 + (tg >> 1);
            const float b0 = sbias[g0*128 + j];
            const float b1 = sbias[g1*128 + j];
#pragma unroll
            for (int mi = 0; mi < 4; mi++) {
                __half2 a = __floats2half2_rn(d[mi][ni][0] + b0, d[mi][ni][1] + b1);
                __half2 b = __floats2half2_rn(d[mi][ni][2] + b0, d[mi][ni][3] + b1);
                lo2[mi][ni] = *(uint32_t*)&a;
                hi2[mi][ni] = *(uint32_t*)&b;
            }
        }
        const uint32_t coff = (q4*4 + nw)*64 + tg*16;
#pragma unroll
        for (int mi = 0; mi < 4; mi++) {
            int rlo = row0 + mw*64 + mi*16 + g;
            int rhi = rlo + 8;
            if (rlo < NTOT)
                *(uint4*)(g_gn + (size_t)rlo*1024 + coff) =
                    make_uint4(lo2[mi][0], lo2[mi][1], lo2[mi][2], lo2[mi][3]);
            if (rhi < NTOT)
                *(uint4*)(g_gn + (size_t)rhi*1024 + coff) =
                    make_uint4(hi2[mi][0], hi2[mi][1], hi2[mi][2], hi2[mi][3]);
        }
    }
}

// ---------------------------------------------------------------------------
// LSTM: single CTA, 64 seqs, 512 thr (16 warps x [64m x 32n]), Whh resident,
// double-buffered h tile, ONE __syncthreads per step. No clusters.
// ---------------------------------------------------------------------------
__global__ void __launch_bounds__(512, 1)
lstm_mma(float* __restrict__ out) {
    extern __shared__ __align__(16) char smem[];
    const uint32_t sb = smem_u32(smem);
    const int tid  = threadIdx.x;
    const int wid  = tid >> 5, lane = tid & 31;
    const int g    = lane >> 2, tg = lane & 3;
    const int nw   = wid;                      // 16 n-warps, full 512 gate cols
    const int bt0  = blockIdx.x * 64;

    if (tid == 0) {
        mbar_init(sb + SL_MBAR, 1);
        fence_async();
        mbar_expect_tx(sb + SL_MBAR, 2*HALFB);
        // Whh halves concatenated: rows [0,256) = j 0..63, rows [256,512) = j 64..127
        bulk_g2s(sb + SL_W,         (const char*)g_Bimg + HALFB,       HALFB, sb + SL_MBAR);
        bulk_g2s(sb + SL_W + HALFB, (const char*)g_Bimg + WB2 + HALFB, HALFB, sb + SL_MBAR);
    }
    int* snid = (int*)(smem + SL_NID);
    int* sact = (int*)(smem + SL_ACT);
    for (int i = tid; i < 64*PP; i += 512) snid[i] = g_nids[bt0*PP + i];
    if (tid < 64) sact[tid] = g_active[bt0 + tid];
    __syncthreads();

    const uint32_t ab0 = sb + SL_AH0 + (lane & 15)*ROWB + ((lane & 16) ? 16u : 0u);
    const uint32_t ab1 = sb + SL_AH1 + (lane & 15)*ROWB + ((lane & 16) ? 16u : 0u);
    const int rbase = g + ((tg & 1) ? 8 : 0);
    const unsigned char* gbase = g_gn + nw*64 + tg*16;

    float creg[16];
#pragma unroll
    for (int i = 0; i < 16; i++) creg[i] = 0.0f;

    bool wready = false;

    for (int p = 0; p < PP; p++) {
        // ---- init d from gnode (fragment-permuted; coalesced LDG.128) ----
        uint4 fr[8];
#pragma unroll
        for (int mi = 0; mi < 4; mi++) {
            const int rlo = mi*16 + g, rhi = rlo + 8;
            fr[2*mi]   = *(const uint4*)(gbase + (size_t)snid[rlo*PP + p]*1024);
            fr[2*mi+1] = *(const uint4*)(gbase + (size_t)snid[rhi*PP + p]*1024);
        }
        float d[4][4][4];
#pragma unroll
        for (int mi = 0; mi < 4; mi++) {
            const uint32_t* lo = (const uint32_t*)&fr[2*mi];
            const uint32_t* hi = (const uint32_t*)&fr[2*mi+1];
#pragma unroll
            for (int ni = 0; ni < 4; ni++) {
                float2 vlo = __half22float2(*(const __half2*)&lo[ni]);
                float2 vhi = __half22float2(*(const __half2*)&hi[ni]);
                d[mi][ni][0] = vlo.x; d[mi][ni][1] = vlo.y;
                d[mi][ni][2] = vhi.x; d[mi][ni][3] = vhi.y;
            }
        }

        if (p > 0) {
            if (!wready) { mbar_wait(sb + SL_MBAR, 0); wready = true; }
            // read h written at step p-1: buffer (p-1)&1
            gemm_pass(((p - 1) & 1) ? ab1 : ab0, smem + SL_W, nw, g, tg, d);
        }

        // ---- epilogue: gates -> c, h; write h to buffer p&1 ----
        char* wrbuf = smem + ((p & 1) ? SL_AH1 : SL_AH0);
#pragma unroll
        for (int ni = 0; ni < 4; ni++) {
            const int j = nw*8 + ni*2 + (tg >> 1);
#pragma unroll
            for (int mi = 0; mi < 4; mi++) {
                float d0 = d[mi][ni][0], d1 = d[mi][ni][1];
                float d2 = d[mi][ni][2], d3 = d[mi][ni][3];
                float s0 = __shfl_xor_sync(0xffffffffu, d0, 1);
                float s1 = __shfl_xor_sync(0xffffffffu, d1, 1);
                float s2 = __shfl_xor_sync(0xffffffffu, d2, 1);
                float s3 = __shfl_xor_sync(0xffffffffu, d3, 1);
                float gi, gf, gg, go;
                if ((tg & 1) == 0) { gi = d0; gf = d1; gg = s0; go = s1; }
                else               { gi = s2; gf = s3; gg = d2; go = d3; }
                float& cc = creg[mi*4 + ni];
                cc = sigf(gf) * cc + sigf(gi) * tanhf_(gg);
                float h = sigf(go) * tanhf_(cc);
                const int r = rbase + mi*16;
                if (p < PP - 1) {
                    *(__half*)(wrbuf + r*ROWB + j*2) = __float2half(h);
                } else {
                    out[(size_t)(bt0 + r)*DD + j] = sact[r] ? h : 0.0f;
                }
            }
        }

        if (p < PP - 1) __syncthreads();   // h writes visible before next reads
    }
}

// ---------------------------------------------------------------------------
extern "C" void kernel_launch(void* const* d_in, const int* in_sizes, int n_in,
                              void* d_out, int out_size) {
    const float* cross    = (const float*)d_in[0];
    const float* node_emb = (const float*)d_in[1];
    const float* w_ih     = (const float*)d_in[2];
    const float* w_hh     = (const float*)d_in[3];
    const float* b_ih     = (const float*)d_in[4];
    const float* b_hh     = (const float*)d_in[5];
    const int*   paths    = (const int*)d_in[6];
    float* out = (float*)d_out;

    cudaFuncSetAttribute(gnode_kernel, cudaFuncAttributeMaxDynamicSharedMemorySize, SMEM_A);
    cudaFuncSetAttribute(lstm_mma, cudaFuncAttributeMaxDynamicSharedMemorySize, SMEM_L);

    prep_kernel<<<(2*NG*DD + 255)/256, 256>>>(w_ih, w_hh, b_ih, b_hh);
    leaf_kernel<<<(NSEQ*32 + 127)/128, 128>>>(cross, paths);
    gnode_kernel<<<(NTOT + 127)/128, 256, SMEM_A>>>(node_emb);
    lstm_mma<<<NSEQ/64, 512, SMEM_L>>>(out);
}

// round 15
// speedup vs baseline: 3.4372x; 1.6832x over previous
#include <cuda_runtime.h>
#include <cuda_fp16.h>
#include <cstdint>

#define BB   512
#define TT   100
#define LL   256
#define DD   128
#define PP   9
#define NSEQ (BB*TT)
#define NG   512
#define NTOT (TT*(2*LL-1))   // 51100 nodes
#define ROWB  272            // padded row stride bytes
#define HALFB (256*ROWB)     // 69632: one part for one rank (256 gate-rows)
#define WB2   (2*HALFB)      // per-rank [Wih | Whh]

// ---- prep image (R12/R13 layout, validated): [rank][part][n_local][k] fp16 ----
__device__ __align__(128) unsigned char g_Bimg[2*WB2];
__device__ float g_bias[NG];
__device__ int   g_nids[NSEQ*PP];
__device__ int   g_active[NSEQ];
// per-node gate table, fragment-permuted fp16 (R13-validated)
__device__ __align__(128) unsigned char g_gn[(size_t)NTOT*1024];

// ---- gnode kernel SMEM ----
#define SA_W0   0
#define SA_W1   69632
#define SA_X    139264
#define SA_BIAS 174080
#define SA_MBAR 176128
#define SMEM_A  176256

// ---- LSTM kernel SMEM (single CTA, no cluster) ----
#define SL_W    0            // 139264 Whh resident (512 gate-rows)
#define SL_AH0  139264       // 17408 h tile buf0
#define SL_AH1  156672       // 17408 h tile buf1
#define SL_NID  174080       // 2304
#define SL_ACT  176384       // 256
#define SL_MBAR 176640       // 8
#define SMEM_L  176768

// HW tanh (sm_75+): 1 MUFU op
__device__ __forceinline__ float tanha(float x) {
    float y; asm("tanh.approx.f32 %0, %1;" : "=f"(y) : "f"(x)); return y;
}
__device__ __forceinline__ float siga(float x) {
    return fmaf(tanha(0.5f * x), 0.5f, 0.5f);
}

__device__ __forceinline__ uint32_t smem_u32(const void* p) {
    uint32_t a;
    asm("{ .reg .u64 t; cvta.to.shared.u64 t, %1; cvt.u32.u64 %0, t; }" : "=r"(a) : "l"(p));
    return a;
}
__device__ __forceinline__ void mbar_init(uint32_t mbar, uint32_t cnt) {
    asm volatile("mbarrier.init.shared.b64 [%0], %1;" :: "r"(mbar), "r"(cnt) : "memory");
}
__device__ __forceinline__ void mbar_expect_tx(uint32_t mbar, uint32_t bytes) {
    asm volatile("mbarrier.arrive.expect_tx.shared.b64 _, [%0], %1;" :: "r"(mbar), "r"(bytes) : "memory");
}
__device__ __forceinline__ void mbar_wait(uint32_t mbar, uint32_t ph) {
    asm volatile(
        "{\n\t.reg .pred P;\n\tLW_%=:\n\t"
        "mbarrier.try_wait.parity.acquire.cta.shared::cta.b64 P, [%0], %1, 0x989680;\n\t"
        "@P bra LD_%=;\n\tbra LW_%=;\n\tLD_%=:\n\t}"
        :: "r"(mbar), "r"(ph) : "memory");
}
__device__ __forceinline__ void bulk_g2s(uint32_t dst, const void* src, uint32_t bytes, uint32_t mbar) {
    asm volatile(
        "cp.async.bulk.shared::cluster.global.mbarrier::complete_tx::bytes [%0], [%1], %2, [%3];"
        :: "r"(dst), "l"(src), "r"(bytes), "r"(mbar) : "memory");
}
__device__ __forceinline__ void fence_async() {
    asm volatile("fence.proxy.async.shared::cta;" ::: "memory");
}
__device__ __forceinline__ void mma16816h(float* d, const uint32_t* a, const uint32_t* b) {
    asm volatile(
        "mma.sync.aligned.m16n8k16.row.col.f32.f16.f16.f32 "
        "{%0,%1,%2,%3}, {%4,%5,%6,%7}, {%8,%9}, {%0,%1,%2,%3};"
        : "+f"(d[0]), "+f"(d[1]), "+f"(d[2]), "+f"(d[3])
        : "r"(a[0]), "r"(a[1]), "r"(a[2]), "r"(a[3]), "r"(b[0]), "r"(b[1]));
}
__device__ __forceinline__ void ldsm4(uint32_t* r, uint32_t addr) {
    asm volatile("ldmatrix.sync.aligned.m8n8.x4.shared.b16 {%0,%1,%2,%3}, [%4];"
        : "=r"(r[0]), "=r"(r[1]), "=r"(r[2]), "=r"(r[3]) : "r"(addr));
}

// One [64m x 32n x 128k] warp product-accumulate (fp16).
__device__ __forceinline__ void gemm_pass(uint32_t abase, const char* __restrict__ W,
                                          int nw, int g, int tg, float d[4][4][4]) {
#pragma unroll
    for (int k8 = 0; k8 < 8; k8++) {
        uint32_t a[4][4], b[4][2];
#pragma unroll
        for (int mi = 0; mi < 4; mi++)
            ldsm4(a[mi], abase + mi*(16*ROWB) + k8*32);
        const int kb = (k8*16 + tg*2) * 2;
#pragma unroll
        for (int ni = 0; ni < 4; ni++) {
            const char* wr = W + (nw*32 + ni*8 + g)*ROWB + kb;
            b[ni][0] = *(const uint32_t*)wr;
            b[ni][1] = *(const uint32_t*)(wr + 16);
        }
#pragma unroll
        for (int mi = 0; mi < 4; mi++)
#pragma unroll
            for (int ni = 0; ni < 4; ni++)
                mma16816h(d[mi][ni], a[mi], b[ni]);
    }
}

// ---------------------------------------------------------------------------
__global__ void prep_kernel(const float* __restrict__ w_ih, const float* __restrict__ w_hh,
                            const float* __restrict__ b_ih, const float* __restrict__ b_hh) {
    int idx = blockIdx.x * blockDim.x + threadIdx.x;
    if (idx < NG) g_bias[idx] = b_ih[idx] + b_hh[idx];
    if (idx >= 2 * NG * DD) return;
    int part = idx >> 16;
    int rem  = idx & 65535;
    int r = rem >> 7;
    int k = rem & 127;
    int gate = r >> 7, j = r & 127;
    int rk = j >> 6, jl = j & 63;
    int n = (jl << 2) | gate;
    float w = (part == 0) ? w_ih[r * DD + k] : w_hh[r * DD + k];
    *(__half*)((char*)g_Bimg + rk*WB2 + part*HALFB + n*ROWB + k*2) = __float2half(w);
}

// ---------------------------------------------------------------------------
__global__ void leaf_kernel(const float* __restrict__ cross, const int* __restrict__ paths) {
    int warp = (blockIdx.x * blockDim.x + threadIdx.x) >> 5;
    int lane = threadIdx.x & 31;
    if (warp >= NSEQ) return;
    int b = warp / TT;
    int t = warp - b * TT;
    const float* row = cross + (size_t)b * (TT*LL) + (size_t)t * LL;
    float bv = -3.0e38f; int bl = 0; int anyp = 0;
#pragma unroll
    for (int i = 0; i < LL/32; i++) {
        int l = lane + 32*i;
        float v = row[l];
        if (v > 0.0f) anyp = 1;
        if (v > bv) { bv = v; bl = l; }
    }
#pragma unroll
    for (int off = 16; off > 0; off >>= 1) {
        float ov = __shfl_down_sync(0xffffffffu, bv, off);
        int   ol = __shfl_down_sync(0xffffffffu, bl, off);
        if (ov > bv || (ov == bv && ol < bl)) { bv = ov; bl = ol; }
    }
    anyp = __any_sync(0xffffffffu, anyp);
    int leaf = __shfl_sync(0xffffffffu, bl, 0);
    if (lane < PP) g_nids[warp*PP + lane] = paths[((size_t)t*LL + leaf)*PP + lane];
    if (lane == 0) g_active[warp] = anyp;
}

// ---------------------------------------------------------------------------
// gnode: unchanged from R13/R14 (validated)
// ---------------------------------------------------------------------------
__global__ void __launch_bounds__(256, 1)
gnode_kernel(const float* __restrict__ node_emb) {
    extern __shared__ __align__(16) char smem[];
    const uint32_t sb = smem_u32(smem);
    const int tid  = threadIdx.x;
    const int wid  = tid >> 5, lane = tid & 31;
    const int g    = lane >> 2, tg = lane & 3;
    const int mw   = wid >> 2, nw = wid & 3;
    const int row0 = blockIdx.x * 128;

    if (tid == 0) {
        mbar_init(sb + SA_MBAR, 1);
        fence_async();
        mbar_expect_tx(sb + SA_MBAR, 2*HALFB);
        bulk_g2s(sb + SA_W0, (const char*)g_Bimg,       HALFB, sb + SA_MBAR);
        bulk_g2s(sb + SA_W1, (const char*)g_Bimg + WB2, HALFB, sb + SA_MBAR);
    }
    float* sbias = (float*)(smem + SA_BIAS);
    for (int i = tid; i < NG; i += 256) sbias[i] = g_bias[i];

#pragma unroll
    for (int i = 0; i < 16; i++) {
        int idx = i * 256 + tid;
        int mm = idx >> 5, kq = (idx & 31) << 2;
        int gr = row0 + mm; if (gr >= NTOT) gr = NTOT - 1;
        const float4 v = *(const float4*)(node_emb + (size_t)gr*DD + kq);
        __half2 a = __floats2half2_rn(v.x, v.y);
        __half2 b = __floats2half2_rn(v.z, v.w);
        uint2 pk; pk.x = *(uint32_t*)&a; pk.y = *(uint32_t*)&b;
        *(uint2*)(smem + SA_X + mm*ROWB + kq*2) = pk;
    }
    mbar_wait(sb + SA_MBAR, 0);
    __syncthreads();

    const uint32_t abase = sb + SA_X + (mw*64 + (lane & 15))*ROWB + ((lane & 16) ? 16u : 0u);
    const int g0 = (2*tg)     & 3;
    const int g1 = (2*tg + 1) & 3;

#pragma unroll
    for (int q4 = 0; q4 < 4; q4++) {
        const char* W = smem + ((q4 >= 2) ? SA_W1 : SA_W0) + (q4 & 1)*(128*ROWB);
        float d[4][4][4];
#pragma unroll
        for (int mi = 0; mi < 4; mi++)
#pragma unroll
            for (int ni = 0; ni < 4; ni++)
#pragma unroll
                for (int e = 0; e < 4; e++) d[mi][ni][e] = 0.0f;
        gemm_pass(abase, W, nw, g, tg, d);

        uint32_t lo2[4][4], hi2[4][4];
#pragma unroll
        for (int ni = 0; ni < 4; ni++) {
            const int j = q4*32 + nw*8 + ni*2 + (tg >> 1);
            const float b0 = sbias[g0*128 + j];
            const float b1 = sbias[g1*128 + j];
#pragma unroll
            for (int mi = 0; mi < 4; mi++) {
                __half2 a = __floats2half2_rn(d[mi][ni][0] + b0, d[mi][ni][1] + b1);
                __half2 b = __floats2half2_rn(d[mi][ni][2] + b0, d[mi][ni][3] + b1);
                lo2[mi][ni] = *(uint32_t*)&a;
                hi2[mi][ni] = *(uint32_t*)&b;
            }
        }
        const uint32_t coff = (q4*4 + nw)*64 + tg*16;
#pragma unroll
        for (int mi = 0; mi < 4; mi++) {
            int rlo = row0 + mw*64 + mi*16 + g;
            int rhi = rlo + 8;
            if (rlo < NTOT)
                *(uint4*)(g_gn + (size_t)rlo*1024 + coff) =
                    make_uint4(lo2[mi][0], lo2[mi][1], lo2[mi][2], lo2[mi][3]);
            if (rhi < NTOT)
                *(uint4*)(g_gn + (size_t)rhi*1024 + coff) =
                    make_uint4(hi2[mi][0], hi2[mi][1], hi2[mi][2], hi2[mi][3]);
        }
    }
}

// ---------------------------------------------------------------------------
// LSTM: single CTA, 64 seqs, 512 thr, Whh resident, double-buffered h,
// ONE sync/step. R15: tanh.approx activations + early gnode prefetch.
// ---------------------------------------------------------------------------
__global__ void __launch_bounds__(512, 1)
lstm_mma(float* __restrict__ out) {
    extern __shared__ __align__(16) char smem[];
    const uint32_t sb = smem_u32(smem);
    const int tid  = threadIdx.x;
    const int wid  = tid >> 5, lane = tid & 31;
    const int g    = lane >> 2, tg = lane & 3;
    const int nw   = wid;
    const int bt0  = blockIdx.x * 64;

    if (tid == 0) {
        mbar_init(sb + SL_MBAR, 1);
        fence_async();
        mbar_expect_tx(sb + SL_MBAR, 2*HALFB);
        bulk_g2s(sb + SL_W,         (const char*)g_Bimg + HALFB,       HALFB, sb + SL_MBAR);
        bulk_g2s(sb + SL_W + HALFB, (const char*)g_Bimg + WB2 + HALFB, HALFB, sb + SL_MBAR);
    }
    int* snid = (int*)(smem + SL_NID);
    int* sact = (int*)(smem + SL_ACT);
    for (int i = tid; i < 64*PP; i += 512) snid[i] = g_nids[bt0*PP + i];
    if (tid < 64) sact[tid] = g_active[bt0 + tid];
    __syncthreads();

    const uint32_t ab0 = sb + SL_AH0 + (lane & 15)*ROWB + ((lane & 16) ? 16u : 0u);
    const uint32_t ab1 = sb + SL_AH1 + (lane & 15)*ROWB + ((lane & 16) ? 16u : 0u);
    const int rbase = g + ((tg & 1) ? 8 : 0);
    const unsigned char* gbase = g_gn + nw*64 + tg*16;

    float creg[16];
#pragma unroll
    for (int i = 0; i < 16; i++) creg[i] = 0.0f;

    bool wready = false;

    // preload gnode fragments for p = 0
    uint4 fr[8];
#pragma unroll
    for (int mi = 0; mi < 4; mi++) {
        const int rlo = mi*16 + g, rhi = rlo + 8;
        fr[2*mi]   = *(const uint4*)(gbase + (size_t)snid[rlo*PP]*1024);
        fr[2*mi+1] = *(const uint4*)(gbase + (size_t)snid[rhi*PP]*1024);
    }

    for (int p = 0; p < PP; p++) {
        // ---- convert fr -> d (fr dead after this) ----
        float d[4][4][4];
#pragma unroll
        for (int mi = 0; mi < 4; mi++) {
            const uint32_t* lo = (const uint32_t*)&fr[2*mi];
            const uint32_t* hi = (const uint32_t*)&fr[2*mi+1];
#pragma unroll
            for (int ni = 0; ni < 4; ni++) {
                float2 vlo = __half22float2(*(const __half2*)&lo[ni]);
                float2 vhi = __half22float2(*(const __half2*)&hi[ni]);
                d[mi][ni][0] = vlo.x; d[mi][ni][1] = vlo.y;
                d[mi][ni][2] = vhi.x; d[mi][ni][3] = vhi.y;
            }
        }
        // ---- early prefetch for p+1: L2 latency hides behind gemm+epilogue ----
        if (p + 1 < PP) {
#pragma unroll
            for (int mi = 0; mi < 4; mi++) {
                const int rlo = mi*16 + g, rhi = rlo + 8;
                fr[2*mi]   = *(const uint4*)(gbase + (size_t)snid[rlo*PP + p + 1]*1024);
                fr[2*mi+1] = *(const uint4*)(gbase + (size_t)snid[rhi*PP + p + 1]*1024);
            }
        }

        if (p > 0) {
            if (!wready) { mbar_wait(sb + SL_MBAR, 0); wready = true; }
            gemm_pass(((p - 1) & 1) ? ab1 : ab0, smem + SL_W, nw, g, tg, d);
        }

        // ---- epilogue: HW-tanh gates; write h to buffer p&1 ----
        char* wrbuf = smem + ((p & 1) ? SL_AH1 : SL_AH0);
#pragma unroll
        for (int ni = 0; ni < 4; ni++) {
            const int j = nw*8 + ni*2 + (tg >> 1);
#pragma unroll
            for (int mi = 0; mi < 4; mi++) {
                float d0 = d[mi][ni][0], d1 = d[mi][ni][1];
                float d2 = d[mi][ni][2], d3 = d[mi][ni][3];
                float s0 = __shfl_xor_sync(0xffffffffu, d0, 1);
                float s1 = __shfl_xor_sync(0xffffffffu, d1, 1);
                float s2 = __shfl_xor_sync(0xffffffffu, d2, 1);
                float s3 = __shfl_xor_sync(0xffffffffu, d3, 1);
                float gi, gf, gg, go;
                if ((tg & 1) == 0) { gi = d0; gf = d1; gg = s0; go = s1; }
                else               { gi = s2; gf = s3; gg = d2; go = d3; }
                float& cc = creg[mi*4 + ni];
                cc = siga(gf) * cc + siga(gi) * tanha(gg);
                float h = siga(go) * tanha(cc);
                const int r = rbase + mi*16;
                if (p < PP - 1) {
                    *(__half*)(wrbuf + r*ROWB + j*2) = __float2half(h);
                } else {
                    out[(size_t)(bt0 + r)*DD + j] = sact[r] ? h : 0.0f;
                }
            }
        }

        if (p < PP - 1) __syncthreads();
    }
}

// ---------------------------------------------------------------------------
extern "C" void kernel_launch(void* const* d_in, const int* in_sizes, int n_in,
                              void* d_out, int out_size) {
    const float* cross    = (const float*)d_in[0];
    const float* node_emb = (const float*)d_in[1];
    const float* w_ih     = (const float*)d_in[2];
    const float* w_hh     = (const float*)d_in[3];
    const float* b_ih     = (const float*)d_in[4];
    const float* b_hh     = (const float*)d_in[5];
    const int*   paths    = (const int*)d_in[6];
    float* out = (float*)d_out;

    cudaFuncSetAttribute(gnode_kernel, cudaFuncAttributeMaxDynamicSharedMemorySize, SMEM_A);
    cudaFuncSetAttribute(lstm_mma, cudaFuncAttributeMaxDynamicSharedMemorySize, SMEM_L);

    prep_kernel<<<(2*NG*DD + 255)/256, 256>>>(w_ih, w_hh, b_ih, b_hh);
    leaf_kernel<<<(NSEQ*32 + 127)/128, 128>>>(cross, paths);
    gnode_kernel<<<(NTOT + 127)/128, 256, SMEM_A>>>(node_emb);
    lstm_mma<<<NSEQ/64, 512, SMEM_L>>>(out);
}

// round 16
// speedup vs baseline: 3.6752x; 1.0692x over previous
#include <cuda_runtime.h>
#include <cuda_fp16.h>
#include <cstdint>

#define BB   512
#define TT   100
#define LL   256
#define DD   128
#define PP   9
#define NSEQ (BB*TT)
#define NG   512
#define NTOT (TT*(2*LL-1))   // 51100 nodes
#define ROWB  272            // padded row stride bytes
#define HALFB (256*ROWB)     // 69632: one part for one rank (256 gate-rows)
#define WB2   (2*HALFB)      // per-rank [Wih | Whh]

// ---- prep image: [rank][part][n_local][k] fp16, gate-BLOCKED rows:
//      n = jhi*32 + gate*8 + jlo  (jhi=j>>3 local to rank, jlo=j&7) ----
__device__ __align__(128) unsigned char g_Bimg[2*WB2];
__device__ float g_bias[NG];
__device__ int   g_nids[NSEQ*PP];
__device__ int   g_active[NSEQ];
// per-node gate table, fragment-permuted fp16 (positional; matches lstm reader)
__device__ __align__(128) unsigned char g_gn[(size_t)NTOT*1024];

// ---- gnode kernel SMEM ----
#define SA_W0   0
#define SA_W1   69632
#define SA_X    139264
#define SA_BIAS 174080
#define SA_MBAR 176128
#define SMEM_A  176256

// ---- LSTM kernel SMEM ----
#define SL_W    0            // 139264 Whh resident (512 gate-rows)
#define SL_AH0  139264       // 17408 h tile buf0
#define SL_AH1  156672       // 17408 h tile buf1
#define SL_NID  174080       // 2304
#define SL_ACT  176384       // 256
#define SL_MBAR 176640       // 8
#define SMEM_L  176768

__device__ __forceinline__ float tanha(float x) {
    float y; asm("tanh.approx.f32 %0, %1;" : "=f"(y) : "f"(x)); return y;
}
__device__ __forceinline__ float siga(float x) {
    return fmaf(tanha(0.5f * x), 0.5f, 0.5f);
}

__device__ __forceinline__ uint32_t smem_u32(const void* p) {
    uint32_t a;
    asm("{ .reg .u64 t; cvta.to.shared.u64 t, %1; cvt.u32.u64 %0, t; }" : "=r"(a) : "l"(p));
    return a;
}
__device__ __forceinline__ void mbar_init(uint32_t mbar, uint32_t cnt) {
    asm volatile("mbarrier.init.shared.b64 [%0], %1;" :: "r"(mbar), "r"(cnt) : "memory");
}
__device__ __forceinline__ void mbar_expect_tx(uint32_t mbar, uint32_t bytes) {
    asm volatile("mbarrier.arrive.expect_tx.shared.b64 _, [%0], %1;" :: "r"(mbar), "r"(bytes) : "memory");
}
__device__ __forceinline__ void mbar_wait(uint32_t mbar, uint32_t ph) {
    asm volatile(
        "{\n\t.reg .pred P;\n\tLW_%=:\n\t"
        "mbarrier.try_wait.parity.acquire.cta.shared::cta.b64 P, [%0], %1, 0x989680;\n\t"
        "@P bra LD_%=;\n\tbra LW_%=;\n\tLD_%=:\n\t}"
        :: "r"(mbar), "r"(ph) : "memory");
}
__device__ __forceinline__ void bulk_g2s(uint32_t dst, const void* src, uint32_t bytes, uint32_t mbar) {
    asm volatile(
        "cp.async.bulk.shared::cluster.global.mbarrier::complete_tx::bytes [%0], [%1], %2, [%3];"
        :: "r"(dst), "l"(src), "r"(bytes), "r"(mbar) : "memory");
}
__device__ __forceinline__ void fence_async() {
    asm volatile("fence.proxy.async.shared::cta;" ::: "memory");
}
__device__ __forceinline__ void mma16816h(float* d, const uint32_t* a, const uint32_t* b) {
    asm volatile(
        "mma.sync.aligned.m16n8k16.row.col.f32.f16.f16.f32 "
        "{%0,%1,%2,%3}, {%4,%5,%6,%7}, {%8,%9}, {%0,%1,%2,%3};"
        : "+f"(d[0]), "+f"(d[1]), "+f"(d[2]), "+f"(d[3])
        : "r"(a[0]), "r"(a[1]), "r"(a[2]), "r"(a[3]), "r"(b[0]), "r"(b[1]));
}
__device__ __forceinline__ void ldsm4(uint32_t* r, uint32_t addr) {
    asm volatile("ldmatrix.sync.aligned.m8n8.x4.shared.b16 {%0,%1,%2,%3}, [%4];"
        : "=r"(r[0]), "=r"(r[1]), "=r"(r[2]), "=r"(r[3]) : "r"(addr));
}

// One [64m x 32n x 128k] warp product-accumulate (fp16).
__device__ __forceinline__ void gemm_pass(uint32_t abase, const char* __restrict__ W,
                                          int nw, int g, int tg, float d[4][4][4]) {
#pragma unroll
    for (int k8 = 0; k8 < 8; k8++) {
        uint32_t a[4][4], b[4][2];
#pragma unroll
        for (int mi = 0; mi < 4; mi++)
            ldsm4(a[mi], abase + mi*(16*ROWB) + k8*32);
        const int kb = (k8*16 + tg*2) * 2;
#pragma unroll
        for (int ni = 0; ni < 4; ni++) {
            const char* wr = W + (nw*32 + ni*8 + g)*ROWB + kb;
            b[ni][0] = *(const uint32_t*)wr;
            b[ni][1] = *(const uint32_t*)(wr + 16);
        }
#pragma unroll
        for (int mi = 0; mi < 4; mi++)
#pragma unroll
            for (int ni = 0; ni < 4; ni++)
                mma16816h(d[mi][ni], a[mi], b[ni]);
    }
}

// ---------------------------------------------------------------------------
// prep: gate-BLOCKED rows. rank rk = j>>6; n_local = (jhi&7)*32 + gate*8 + jlo
// ---------------------------------------------------------------------------
__global__ void prep_kernel(const float* __restrict__ w_ih, const float* __restrict__ w_hh,
                            const float* __restrict__ b_ih, const float* __restrict__ b_hh) {
    int idx = blockIdx.x * blockDim.x + threadIdx.x;
    if (idx < NG) g_bias[idx] = b_ih[idx] + b_hh[idx];
    if (idx >= 2 * NG * DD) return;
    int part = idx >> 16;
    int rem  = idx & 65535;
    int r = rem >> 7;              // gate*128 + j
    int k = rem & 127;
    int gate = r >> 7, j = r & 127;
    int jhi = j >> 3, jlo = j & 7;
    int rk = jhi >> 3;
    int n = (jhi & 7)*32 + gate*8 + jlo;
    float w = (part == 0) ? w_ih[r * DD + k] : w_hh[r * DD + k];
    *(__half*)((char*)g_Bimg + rk*WB2 + part*HALFB + n*ROWB + k*2) = __float2half(w);
}

// ---------------------------------------------------------------------------
__global__ void leaf_kernel(const float* __restrict__ cross, const int* __restrict__ paths) {
    int warp = (blockIdx.x * blockDim.x + threadIdx.x) >> 5;
    int lane = threadIdx.x & 31;
    if (warp >= NSEQ) return;
    int b = warp / TT;
    int t = warp - b * TT;
    const float* row = cross + (size_t)b * (TT*LL) + (size_t)t * LL;
    float bv = -3.0e38f; int bl = 0; int anyp = 0;
#pragma unroll
    for (int i = 0; i < LL/32; i++) {
        int l = lane + 32*i;
        float v = row[l];
        if (v > 0.0f) anyp = 1;
        if (v > bv) { bv = v; bl = l; }
    }
#pragma unroll
    for (int off = 16; off > 0; off >>= 1) {
        float ov = __shfl_down_sync(0xffffffffu, bv, off);
        int   ol = __shfl_down_sync(0xffffffffu, bl, off);
        if (ov > bv || (ov == bv && ol < bl)) { bv = ov; bl = ol; }
    }
    anyp = __any_sync(0xffffffffu, anyp);
    int leaf = __shfl_sync(0xffffffffu, bl, 0);
    if (lane < PP) g_nids[warp*PP + lane] = paths[((size_t)t*LL + leaf)*PP + lane];
    if (lane == 0) g_active[warp] = anyp;
}

// ---------------------------------------------------------------------------
// gnode: gnode[node] = node_emb[node] @ Wih^T + bias (fp16, fragment-permuted)
// gate-blocked: col n -> gate = ni, j = (q4*4+nw)*8 + 2tg + e
// ---------------------------------------------------------------------------
__global__ void __launch_bounds__(256, 1)
gnode_kernel(const float* __restrict__ node_emb) {
    extern __shared__ __align__(16) char smem[];
    const uint32_t sb = smem_u32(smem);
    const int tid  = threadIdx.x;
    const int wid  = tid >> 5, lane = tid & 31;
    const int g    = lane >> 2, tg = lane & 3;
    const int mw   = wid >> 2, nw = wid & 3;
    const int row0 = blockIdx.x * 128;

    if (tid == 0) {
        mbar_init(sb + SA_MBAR, 1);
        fence_async();
        mbar_expect_tx(sb + SA_MBAR, 2*HALFB);
        bulk_g2s(sb + SA_W0, (const char*)g_Bimg,       HALFB, sb + SA_MBAR);
        bulk_g2s(sb + SA_W1, (const char*)g_Bimg + WB2, HALFB, sb + SA_MBAR);
    }
    float* sbias = (float*)(smem + SA_BIAS);
    for (int i = tid; i < NG; i += 256) sbias[i] = g_bias[i];

#pragma unroll
    for (int i = 0; i < 16; i++) {
        int idx = i * 256 + tid;
        int mm = idx >> 5, kq = (idx & 31) << 2;
        int gr = row0 + mm; if (gr >= NTOT) gr = NTOT - 1;
        const float4 v = *(const float4*)(node_emb + (size_t)gr*DD + kq);
        __half2 a = __floats2half2_rn(v.x, v.y);
        __half2 b = __floats2half2_rn(v.z, v.w);
        uint2 pk; pk.x = *(uint32_t*)&a; pk.y = *(uint32_t*)&b;
        *(uint2*)(smem + SA_X + mm*ROWB + kq*2) = pk;
    }
    mbar_wait(sb + SA_MBAR, 0);
    __syncthreads();

    const uint32_t abase = sb + SA_X + (mw*64 + (lane & 15))*ROWB + ((lane & 16) ? 16u : 0u);

#pragma unroll
    for (int q4 = 0; q4 < 4; q4++) {
        const char* W = smem + ((q4 >= 2) ? SA_W1 : SA_W0) + (q4 & 1)*(128*ROWB);
        float d[4][4][4];
#pragma unroll
        for (int mi = 0; mi < 4; mi++)
#pragma unroll
            for (int ni = 0; ni < 4; ni++)
#pragma unroll
                for (int e = 0; e < 4; e++) d[mi][ni][e] = 0.0f;
        gemm_pass(abase, W, nw, g, tg, d);

        uint32_t lo2[4][4], hi2[4][4];
#pragma unroll
        for (int ni = 0; ni < 4; ni++) {
            // gate = ni, j = (q4*4+nw)*8 + 2tg + e
            const int j0 = (q4*4 + nw)*8 + 2*tg;
            const float b0 = sbias[ni*128 + j0];
            const float b1 = sbias[ni*128 + j0 + 1];
#pragma unroll
            for (int mi = 0; mi < 4; mi++) {
                __half2 a = __floats2half2_rn(d[mi][ni][0] + b0, d[mi][ni][1] + b1);
                __half2 b = __floats2half2_rn(d[mi][ni][2] + b0, d[mi][ni][3] + b1);
                lo2[mi][ni] = *(uint32_t*)&a;
                hi2[mi][ni] = *(uint32_t*)&b;
            }
        }
        const uint32_t coff = (q4*4 + nw)*64 + tg*16;
#pragma unroll
        for (int mi = 0; mi < 4; mi++) {
            int rlo = row0 + mw*64 + mi*16 + g;
            int rhi = rlo + 8;
            if (rlo < NTOT)
                *(uint4*)(g_gn + (size_t)rlo*1024 + coff) =
                    make_uint4(lo2[mi][0], lo2[mi][1], lo2[mi][2], lo2[mi][3]);
            if (rhi < NTOT)
                *(uint4*)(g_gn + (size_t)rhi*1024 + coff) =
                    make_uint4(hi2[mi][0], hi2[mi][1], hi2[mi][2], hi2[mi][3]);
        }
    }
}

// ---------------------------------------------------------------------------
// LSTM: single CTA, 64 seqs, 512 thr, Whh resident, double-buffered h,
// ONE sync/step. R16: shuffle-free epilogue (gate = ni block).
// ---------------------------------------------------------------------------
__global__ void __launch_bounds__(512, 1)
lstm_mma(float* __restrict__ out) {
    extern __shared__ __align__(16) char smem[];
    const uint32_t sb = smem_u32(smem);
    const int tid  = threadIdx.x;
    const int wid  = tid >> 5, lane = tid & 31;
    const int g    = lane >> 2, tg = lane & 3;
    const int nw   = wid;
    const int bt0  = blockIdx.x * 64;

    if (tid == 0) {
        mbar_init(sb + SL_MBAR, 1);
        fence_async();
        mbar_expect_tx(sb + SL_MBAR, 2*HALFB);
        bulk_g2s(sb + SL_W,         (const char*)g_Bimg + HALFB,       HALFB, sb + SL_MBAR);
        bulk_g2s(sb + SL_W + HALFB, (const char*)g_Bimg + WB2 + HALFB, HALFB, sb + SL_MBAR);
    }
    int* snid = (int*)(smem + SL_NID);
    int* sact = (int*)(smem + SL_ACT);
    for (int i = tid; i < 64*PP; i += 512) snid[i] = g_nids[bt0*PP + i];
    if (tid < 64) sact[tid] = g_active[bt0 + tid];
    __syncthreads();

    const uint32_t ab0 = sb + SL_AH0 + (lane & 15)*ROWB + ((lane & 16) ? 16u : 0u);
    const uint32_t ab1 = sb + SL_AH1 + (lane & 15)*ROWB + ((lane & 16) ? 16u : 0u);
    const int j0 = nw*8 + 2*tg;                 // two adjacent j cols per thread
    const unsigned char* gbase = g_gn + nw*64 + tg*16;

    float creg[16];
#pragma unroll
    for (int i = 0; i < 16; i++) creg[i] = 0.0f;

    bool wready = false;

    // preload gnode fragments for p = 0
    uint4 fr[8];
#pragma unroll
    for (int mi = 0; mi < 4; mi++) {
        const int rlo = mi*16 + g, rhi = rlo + 8;
        fr[2*mi]   = *(const uint4*)(gbase + (size_t)snid[rlo*PP]*1024);
        fr[2*mi+1] = *(const uint4*)(gbase + (size_t)snid[rhi*PP]*1024);
    }

    for (int p = 0; p < PP; p++) {
        // ---- convert fr -> d ----
        float d[4][4][4];
#pragma unroll
        for (int mi = 0; mi < 4; mi++) {
            const uint32_t* lo = (const uint32_t*)&fr[2*mi];
            const uint32_t* hi = (const uint32_t*)&fr[2*mi+1];
#pragma unroll
            for (int ni = 0; ni < 4; ni++) {
                float2 vlo = __half22float2(*(const __half2*)&lo[ni]);
                float2 vhi = __half22float2(*(const __half2*)&hi[ni]);
                d[mi][ni][0] = vlo.x; d[mi][ni][1] = vlo.y;
                d[mi][ni][2] = vhi.x; d[mi][ni][3] = vhi.y;
            }
        }
        // ---- early prefetch for p+1 ----
        if (p + 1 < PP) {
#pragma unroll
            for (int mi = 0; mi < 4; mi++) {
                const int rlo = mi*16 + g, rhi = rlo + 8;
                fr[2*mi]   = *(const uint4*)(gbase + (size_t)snid[rlo*PP + p + 1]*1024);
                fr[2*mi+1] = *(const uint4*)(gbase + (size_t)snid[rhi*PP + p + 1]*1024);
            }
        }

        if (p > 0) {
            if (!wready) { mbar_wait(sb + SL_MBAR, 0); wready = true; }
            gemm_pass(((p - 1) & 1) ? ab1 : ab0, smem + SL_W, nw, g, tg, d);
        }

        // ---- epilogue: gate = ni block; zero shuffles ----
        char* wrbuf = smem + ((p & 1) ? SL_AH1 : SL_AH0);
#pragma unroll
        for (int mi = 0; mi < 4; mi++) {
#pragma unroll
            for (int rh = 0; rh < 2; rh++) {
                const int r = mi*16 + g + rh*8;
                float hv[2];
#pragma unroll
                for (int e = 0; e < 2; e++) {
                    const int idx = rh*2 + e;
                    float gi = d[mi][0][idx], gf = d[mi][1][idx];
                    float gg = d[mi][2][idx], go = d[mi][3][idx];
                    float& cc = creg[mi*4 + rh*2 + e];
                    cc = siga(gf) * cc + siga(gi) * tanha(gg);
                    hv[e] = siga(go) * tanha(cc);
                }
                if (p < PP - 1) {
                    *(__half2*)(wrbuf + r*ROWB + j0*2) = __floats2half2_rn(hv[0], hv[1]);
                } else {
                    const float m = sact[r] ? 1.0f : 0.0f;
                    float2 o; o.x = hv[0]*m; o.y = hv[1]*m;
                    *(float2*)(out + (size_t)(bt0 + r)*DD + j0) = o;
                }
            }
        }

        if (p < PP - 1) __syncthreads();
    }
}

// ---------------------------------------------------------------------------
extern "C" void kernel_launch(void* const* d_in, const int* in_sizes, int n_in,
                              void* d_out, int out_size) {
    const float* cross    = (const float*)d_in[0];
    const float* node_emb = (const float*)d_in[1];
    const float* w_ih     = (const float*)d_in[2];
    const float* w_hh     = (const float*)d_in[3];
    const float* b_ih     = (const float*)d_in[4];
    const float* b_hh     = (const float*)d_in[5];
    const int*   paths    = (const int*)d_in[6];
    float* out = (float*)d_out;

    cudaFuncSetAttribute(gnode_kernel, cudaFuncAttributeMaxDynamicSharedMemorySize, SMEM_A);
    cudaFuncSetAttribute(lstm_mma, cudaFuncAttributeMaxDynamicSharedMemorySize, SMEM_L);

    prep_kernel<<<(2*NG*DD + 255)/256, 256>>>(w_ih, w_hh, b_ih, b_hh);
    leaf_kernel<<<(NSEQ*32 + 127)/128, 128>>>(cross, paths);
    gnode_kernel<<<(NTOT + 127)/128, 256, SMEM_A>>>(node_emb);
    lstm_mma<<<NSEQ/64, 512, SMEM_L>>>(out);
}